// round 7
// baseline (speedup 1.0000x reference)
#include <cuda_runtime.h>
#include <cuda_bf16.h>
#include <cuda_fp16.h>
#include <math.h>
#include <stdint.h>

// Problem constants
#define Bn 2048
#define Cn 50000
#define Dn 128
#define CPAD 50048            // Cn padded to multiple of 64
#define NCT (CPAD / 64)       // 782 column tiles
#define NRT (Bn / 128)        // 16 row tiles
#define Sf 20.0f
#define EPSf 1e-7f
#define COS_M 0.9950041652780258f
#define SIN_M 0.09983341664682815f

#define INV127 (1.0f / 127.0f)
#define S2Q 32258.0f                      // 127 * 254
#define C11 (1.0f / (127.0f * 127.0f))
#define C12 (1.0f / (127.0f * 32258.0f))

// int8 quant scratch, packed 4/word, row-major: [row][32 words]
__device__ __align__(16) uint32_t g_A1[(size_t)Bn * 32];
__device__ __align__(16) uint32_t g_A2[(size_t)Bn * 32];
__device__ __align__(16) uint32_t g_B1[(size_t)CPAD * 32];
__device__ __align__(16) uint32_t g_B2[(size_t)CPAD * 32];
// fp16 wf (205 MB)
__device__ __half g_wfh[(size_t)Bn * Cn];
// Per-(row, coltile) partial sums (written unconditionally -> no zeroing)
__device__ float g_psp[(size_t)Bn * NCT];   // sum exp(wf)
__device__ float g_psl[(size_t)Bn * NCT];   // sum exp(20*wf)
__device__ float g_inv[Bn];
__device__ float g_loss[Bn];

// ---------------------------------------------------------------------------
__device__ __forceinline__ void imma16832(int* c, const uint32_t* a,
                                          uint32_t b0, uint32_t b1) {
    asm volatile(
        "mma.sync.aligned.m16n8k32.row.col.s32.s8.s8.s32 "
        "{%0,%1,%2,%3}, {%4,%5,%6,%7}, {%8,%9}, {%0,%1,%2,%3};"
        : "+r"(c[0]), "+r"(c[1]), "+r"(c[2]), "+r"(c[3])
        : "r"(a[0]), "r"(a[1]), "r"(a[2]), "r"(a[3]), "r"(b0), "r"(b1));
}

__device__ __forceinline__ uint32_t pack4(int a, int b, int c, int d) {
    return (uint32_t)(a & 0xff) | ((uint32_t)(b & 0xff) << 8) |
           ((uint32_t)(c & 0xff) << 16) | ((uint32_t)(d & 0xff) << 24);
}
__device__ __forceinline__ int q2clamp(float r) {
    int q = (int)rintf(r * S2Q);
    return max(-127, min(127, q));
}

// ---------------------------------------------------------------------------
// Normalize + quantize fp32 -> int8 digits a1 (v*127) and a2 (residual*32258).
// One warp per row; lane holds cols 4*lane..4*lane+3 = word `lane` of the row.
// Output arrays bound INSIDE device code (device symbols are invalid as
// host-side kernel args).
// ---------------------------------------------------------------------------
__global__ __launch_bounds__(256) void norm_quant(const float* __restrict__ in,
                                                  int nrows, int npad,
                                                  int which) {
    int warp = (blockIdx.x * blockDim.x + threadIdx.x) >> 5;
    int lane = threadIdx.x & 31;
    if (warp >= npad) return;
    float4 v = make_float4(0.f, 0.f, 0.f, 0.f);
    if (warp < nrows) v = ((const float4*)(in + (size_t)warp * Dn))[lane];
    float ss = v.x * v.x + v.y * v.y + v.z * v.z + v.w * v.w;
#pragma unroll
    for (int o = 16; o; o >>= 1) ss += __shfl_xor_sync(0xffffffffu, ss, o);
    float sc = 1.0f / fmaxf(sqrtf(ss), 1e-12f);
    if (warp >= nrows) sc = 0.0f;
    v.x *= sc; v.y *= sc; v.z *= sc; v.w *= sc;

    int ax = (int)rintf(v.x * 127.0f), ay = (int)rintf(v.y * 127.0f);
    int az = (int)rintf(v.z * 127.0f), aw = (int)rintf(v.w * 127.0f);
    int bx = q2clamp(v.x - ax * INV127), by = q2clamp(v.y - ay * INV127);
    int bz = q2clamp(v.z - az * INV127), bw = q2clamp(v.w - aw * INV127);

    uint32_t* d1 = which ? g_B1 : g_A1;
    uint32_t* d2 = which ? g_B2 : g_A2;
    size_t idx = (size_t)warp * 32 + lane;
    d1[idx] = pack4(ax, ay, az, aw);
    d2[idx] = pack4(bx, by, bz, bw);
}

// ---------------------------------------------------------------------------
// int8 IMMA GEMM with fused exp-sum epilogue + fp16 wf store.
// CTA tile 128x64, 256 threads (8 warps of 32x32), full K=128 in SMEM.
// SMEM rows: 36 words (32 data + 4 pad). Total 13824 words = 55296 B.
// ---------------------------------------------------------------------------
#define RW 36
#define WO_A1 0
#define WO_A2 (128 * RW)
#define WO_B1 (2 * 128 * RW)
#define WO_B2 (2 * 128 * RW + 64 * RW)
#define SM_WORDS (2 * 128 * RW + 2 * 64 * RW)
#define SM_TOTAL (SM_WORDS * 4)

__global__ __launch_bounds__(256, 2) void gemm_mma(const float* __restrict__ bias) {
    extern __shared__ uint32_t sw[];
    int t = threadIdx.x;
    int w = t >> 5, lane = t & 31;
    int row0 = blockIdx.x * 128;       // row tile fastest: B tile L2-reused 16x
    int col0 = blockIdx.y * 64;
    int ct = blockIdx.y;

    // ---- copies: global row (8 uint4) -> smem row (9 uint4, last = pad) ----
    {
        uint4* s4 = (uint4*)sw;
        const uint4* ga1 = (const uint4*)(g_A1 + (size_t)row0 * 32);
        const uint4* ga2 = (const uint4*)(g_A2 + (size_t)row0 * 32);
#pragma unroll
        for (int i = 0; i < 4; i++) {              // 1024 uint4 per A array
            int idx = t + i * 256;
            int r = idx >> 3, q = idx & 7;
            s4[(WO_A1 / 4) + r * 9 + q] = ga1[idx];
            s4[(WO_A2 / 4) + r * 9 + q] = ga2[idx];
        }
        const uint4* gb1 = (const uint4*)(g_B1 + (size_t)col0 * 32);
        const uint4* gb2 = (const uint4*)(g_B2 + (size_t)col0 * 32);
#pragma unroll
        for (int i = 0; i < 2; i++) {              // 512 uint4 per B array
            int idx = t + i * 256;
            int r = idx >> 3, q = idx & 7;
            s4[(WO_B1 / 4) + r * 9 + q] = gb1[idx];
            s4[(WO_B2 / 4) + r * 9 + q] = gb2[idx];
        }
    }
    __syncthreads();

    int wr = w & 3;                    // row group: 4 x 32 rows
    int wc = w >> 2;                   // col group: 2 x 32 cols
    int rq = lane >> 2;                // groupID
    int tig = lane & 3;                // threadID_in_group

    int p11[2][4][4], p12[2][4][4];
#pragma unroll
    for (int mt = 0; mt < 2; mt++)
#pragma unroll
        for (int nt = 0; nt < 4; nt++)
#pragma unroll
            for (int i = 0; i < 4; i++) { p11[mt][nt][i] = 0; p12[mt][nt][i] = 0; }

#pragma unroll
    for (int ks = 0; ks < 4; ks++) {               // k32 steps
        int kw = ks * 8;                           // 8 words = 32 bytes
        uint32_t a1[2][4], a2[2][4];
#pragma unroll
        for (int mt = 0; mt < 2; mt++) {
            int r0 = (wr * 32 + mt * 16 + rq) * RW + kw + tig;
            int r1 = r0 + 8 * RW;
            a1[mt][0] = sw[WO_A1 + r0];            // (row=g,   k bytes 4*tig..)
            a1[mt][1] = sw[WO_A1 + r1];            // (row=g+8, k low)
            a1[mt][2] = sw[WO_A1 + r0 + 4];        // (row=g,   k+16)
            a1[mt][3] = sw[WO_A1 + r1 + 4];
            a2[mt][0] = sw[WO_A2 + r0];
            a2[mt][1] = sw[WO_A2 + r1];
            a2[mt][2] = sw[WO_A2 + r0 + 4];
            a2[mt][3] = sw[WO_A2 + r1 + 4];
        }
#pragma unroll
        for (int nt = 0; nt < 4; nt++) {
            int rb = (wc * 32 + nt * 8 + rq) * RW + kw + tig;
            uint32_t b10 = sw[WO_B1 + rb];         // (n=g, k low)
            uint32_t b11 = sw[WO_B1 + rb + 4];     // (n=g, k+16)
            uint32_t b20 = sw[WO_B2 + rb];
            uint32_t b21 = sw[WO_B2 + rb + 4];
#pragma unroll
            for (int mt = 0; mt < 2; mt++) {
                imma16832(p11[mt][nt], a1[mt], b10, b11);   // a1*b1
                imma16832(p12[mt][nt], a1[mt], b20, b21);   // a1*b2
                imma16832(p12[mt][nt], a2[mt], b10, b11);   // a2*b1 (same scale)
            }
        }
    }
    __syncthreads();   // tiles dead; smem reused for row-sum combine

    // ---- epilogue: reconstruct fp32, bias, fp16 store, per-row exp sums ----
    float rsp[4] = {0.f, 0.f, 0.f, 0.f};   // rows mt*16+rq, mt*16+8+rq
    float rsl[4] = {0.f, 0.f, 0.f, 0.f};
    int cq = tig * 2;
#pragma unroll
    for (int nt = 0; nt < 4; nt++) {
        int col = col0 + wc * 32 + nt * 8 + cq;
        if (col >= Cn) continue;
        float2 b2 = *(const float2*)&bias[col];
#pragma unroll
        for (int mt = 0; mt < 2; mt++) {
            int r = row0 + wr * 32 + mt * 16 + rq;
            float v00 = fmaf((float)p11[mt][nt][0], C11,
                        fmaf((float)p12[mt][nt][0], C12, b2.x));
            float v01 = fmaf((float)p11[mt][nt][1], C11,
                        fmaf((float)p12[mt][nt][1], C12, b2.y));
            float v10 = fmaf((float)p11[mt][nt][2], C11,
                        fmaf((float)p12[mt][nt][2], C12, b2.x));
            float v11 = fmaf((float)p11[mt][nt][3], C11,
                        fmaf((float)p12[mt][nt][3], C12, b2.y));
            *(__half2*)&g_wfh[(size_t)r * Cn + col] = __floats2half2_rn(v00, v01);
            *(__half2*)&g_wfh[(size_t)(r + 8) * Cn + col] = __floats2half2_rn(v10, v11);
            rsp[2 * mt]     += __expf(v00) + __expf(v01);
            rsp[2 * mt + 1] += __expf(v10) + __expf(v11);
            rsl[2 * mt]     += __expf(Sf * v00) + __expf(Sf * v01);
            rsl[2 * mt + 1] += __expf(Sf * v10) + __expf(Sf * v11);
        }
    }
    // reduce over the 4 lanes of each row group (tig bits)
#pragma unroll
    for (int j = 0; j < 4; j++) {
        rsp[j] += __shfl_xor_sync(0xffffffffu, rsp[j], 1);
        rsp[j] += __shfl_xor_sync(0xffffffffu, rsp[j], 2);
        rsl[j] += __shfl_xor_sync(0xffffffffu, rsl[j], 1);
        rsl[j] += __shfl_xor_sync(0xffffffffu, rsl[j], 2);
    }
    float* ssp = (float*)sw;           // [2][128]
    float* ssl = ((float*)sw) + 256;   // [2][128]
    if (tig == 0) {
#pragma unroll
        for (int j = 0; j < 4; j++) {
            int lrow = wr * 32 + (j >> 1) * 16 + (j & 1) * 8 + rq;
            ssp[wc * 128 + lrow] = rsp[j];
            ssl[wc * 128 + lrow] = rsl[j];
        }
    }
    __syncthreads();
    if (t < 128) {
        g_psp[(size_t)(row0 + t) * NCT + ct] = ssp[t] + ssp[128 + t];
        g_psl[(size_t)(row0 + t) * NCT + ct] = ssl[t] + ssl[128 + t];
    }
}

// ---------------------------------------------------------------------------
// Per-row: sum partials, fix label term, compute inv + loss. Block per row.
// ---------------------------------------------------------------------------
__global__ __launch_bounds__(256) void row_final(const int* __restrict__ labels) {
    int row = blockIdx.x;
    int t = threadIdx.x;
    __shared__ float red[512];
    float sp = 0.f, sl = 0.f;
    const float* pp = g_psp + (size_t)row * NCT;
    const float* pl = g_psl + (size_t)row * NCT;
    for (int i = t; i < NCT; i += 256) { sp += pp[i]; sl += pl[i]; }
    red[t] = sp; red[256 + t] = sl;
    __syncthreads();
#pragma unroll
    for (int s = 128; s; s >>= 1) {
        if (t < s) { red[t] += red[t + s]; red[256 + t] += red[256 + t + s]; }
        __syncthreads();
    }
    if (t == 0) {
        float spr = red[0], slr = red[256];
        float wl = __half2float(g_wfh[(size_t)row * Cn + labels[row]]);
        float cc = fminf(fmaxf(wl, -1.0f + EPSf), 1.0f - EPSf);
        float cosm = cc * COS_M - sqrtf(fmaxf(1.0f - cc * cc, 0.0f)) * SIN_M;
        float total = slr - __expf(Sf * wl) + __expf(Sf * cosm);
        g_loss[row] = logf(total) - Sf * cosm;
        g_inv[row] = 1.0f / spr;
    }
}

// ---------------------------------------------------------------------------
// Elementwise: pred = exp(wf_fp16) * inv[row].  4 halves -> float4 per thread.
// ---------------------------------------------------------------------------
__global__ __launch_bounds__(256) void finalize(float* __restrict__ out) {
    int row = blockIdx.y;
    int i = blockIdx.x * 256 + threadIdx.x;         // group-of-4 index
    if (i >= Cn / 4) return;
    float inv = g_inv[row];
    const __half2* ph = (const __half2*)(g_wfh + (size_t)row * Cn + 4 * (size_t)i);
    __half2 h01 = ph[0], h23 = ph[1];
    float2 f01 = __half22float2(h01), f23 = __half22float2(h23);
    float4 v;
    v.x = __expf(f01.x) * inv;
    v.y = __expf(f01.y) * inv;
    v.z = __expf(f23.x) * inv;
    v.w = __expf(f23.y) * inv;
    *((float4*)(out + (size_t)row * Cn) + i) = v;
}

// ---------------------------------------------------------------------------
__global__ __launch_bounds__(256) void loss_reduce(float* __restrict__ out) {
    __shared__ float red[256];
    int t = threadIdx.x;
    float s = 0.f;
    for (int i = t; i < Bn; i += 256) s += g_loss[i];
    red[t] = s; __syncthreads();
#pragma unroll
    for (int st = 128; st; st >>= 1) {
        if (t < st) red[t] += red[t + st];
        __syncthreads();
    }
    if (t == 0) out[(size_t)Bn * Cn] = red[0] / (float)Bn;
}

// ---------------------------------------------------------------------------
extern "C" void kernel_launch(void* const* d_in, const int* in_sizes, int n_in,
                              void* d_out, int out_size) {
    const float* x      = (const float*)d_in[0];
    const float* W      = (const float*)d_in[1];
    const float* bias   = (const float*)d_in[2];
    const int*   labels = (const int*)d_in[3];
    float* out = (float*)d_out;

    cudaFuncSetAttribute(gemm_mma, cudaFuncAttributeMaxDynamicSharedMemorySize,
                         SM_TOTAL);

    norm_quant<<<Bn / 8, 256>>>(x, Bn, Bn, 0);
    norm_quant<<<CPAD / 8, 256>>>(W, Cn, CPAD, 1);

    dim3 gg(NRT, NCT);   // row tile fastest -> each B tile loaded once
    gemm_mma<<<gg, 256, SM_TOTAL>>>(bias);

    row_final<<<Bn, 256>>>(labels);

    dim3 gf((Cn / 4 + 255) / 256, Bn);
    finalize<<<gf, 256>>>(out);

    loss_reduce<<<1, 256>>>(out);
}

// round 8
// speedup vs baseline: 1.3988x; 1.3988x over previous
#include <cuda_runtime.h>
#include <cuda_bf16.h>
#include <cuda_fp16.h>
#include <math.h>
#include <stdint.h>

// Problem constants
#define Bn 2048
#define Cn 50000
#define Dn 128
#define CPAD 50048            // Cn padded to multiple of 64
#define NCT (CPAD / 64)       // 782 column tiles
#define NRT (Bn / 128)        // 16 row tiles
#define Sf 20.0f
#define EPSf 1e-7f
#define COS_M 0.9950041652780258f
#define SIN_M 0.09983341664682815f

// Plain row-major bf16 scratch: [row][128]
__device__ __align__(16) __nv_bfloat16 g_Ah[(size_t)Bn * Dn];
__device__ __align__(16) __nv_bfloat16 g_Al[(size_t)Bn * Dn];
__device__ __align__(16) __nv_bfloat16 g_Bh[(size_t)CPAD * Dn];
__device__ __align__(16) __nv_bfloat16 g_Bl[(size_t)CPAD * Dn];
// fp16 wf (205 MB)
__device__ __half g_wfh[(size_t)Bn * Cn];
// Per-(row, coltile) partial sums (written unconditionally -> no zeroing)
__device__ float g_psp[(size_t)Bn * NCT];   // sum exp(wf)
__device__ float g_psl[(size_t)Bn * NCT];   // sum exp(20*wf)
__device__ float g_inv[Bn];
__device__ float g_loss[Bn];

// ---------------------------------------------------------------------------
__device__ __forceinline__ void mma16816(float* c, const uint32_t* a,
                                         uint32_t b0, uint32_t b1) {
    asm volatile(
        "mma.sync.aligned.m16n8k16.row.col.f32.bf16.bf16.f32 "
        "{%0,%1,%2,%3}, {%4,%5,%6,%7}, {%8,%9}, {%0,%1,%2,%3};"
        : "+f"(c[0]), "+f"(c[1]), "+f"(c[2]), "+f"(c[3])
        : "r"(a[0]), "r"(a[1]), "r"(a[2]), "r"(a[3]), "r"(b0), "r"(b1));
}
__device__ __forceinline__ void st_cs_f4(float* p, float4 v) {
    asm volatile("st.global.cs.v4.f32 [%0], {%1,%2,%3,%4};"
                 :: "l"(p), "f"(v.x), "f"(v.y), "f"(v.z), "f"(v.w) : "memory");
}

// ---------------------------------------------------------------------------
// Normalize + split fp32 -> bf16 hi/lo, plain row-major. One warp per row.
// Output arrays bound INSIDE device code (device symbols are invalid as
// host-side kernel args).
// ---------------------------------------------------------------------------
__global__ __launch_bounds__(256) void norm_split(const float* __restrict__ in,
                                                  int nrows, int npad,
                                                  int which) {
    int warp = (blockIdx.x * blockDim.x + threadIdx.x) >> 5;
    int lane = threadIdx.x & 31;
    if (warp >= npad) return;
    float4 v = make_float4(0.f, 0.f, 0.f, 0.f);
    if (warp < nrows) v = ((const float4*)(in + (size_t)warp * Dn))[lane];
    float ss = v.x * v.x + v.y * v.y + v.z * v.z + v.w * v.w;
#pragma unroll
    for (int o = 16; o; o >>= 1) ss += __shfl_xor_sync(0xffffffffu, ss, o);
    float sc = 1.0f / fmaxf(sqrtf(ss), 1e-12f);
    if (warp >= nrows) sc = 0.0f;
    v.x *= sc; v.y *= sc; v.z *= sc; v.w *= sc;

    __nv_bfloat162 h01 = __floats2bfloat162_rn(v.x, v.y);
    __nv_bfloat162 h23 = __floats2bfloat162_rn(v.z, v.w);
    __nv_bfloat162 l01 = __floats2bfloat162_rn(v.x - __bfloat162float(h01.x),
                                               v.y - __bfloat162float(h01.y));
    __nv_bfloat162 l23 = __floats2bfloat162_rn(v.z - __bfloat162float(h23.x),
                                               v.w - __bfloat162float(h23.y));

    __nv_bfloat16* hi = which ? g_Bh : g_Ah;
    __nv_bfloat16* lo = which ? g_Bl : g_Al;
    size_t idx = (size_t)warp * Dn + 4 * lane;
    uint2 hv, lv;
    hv.x = *(uint32_t*)&h01; hv.y = *(uint32_t*)&h23;
    lv.x = *(uint32_t*)&l01; lv.y = *(uint32_t*)&l23;
    *(uint2*)(hi + idx) = hv;
    *(uint2*)(lo + idx) = lv;
}

// ---------------------------------------------------------------------------
// mma.sync bf16 GEMM with fused exp-sum epilogue + fp16 wf store.
// CTA tile 128x64, 256 threads (8 warps of 32x32), full K=128 in SMEM.
// SMEM as uint32 words, row stride 68 (64 data + 4 pad): 104448 bytes.
// ---------------------------------------------------------------------------
#define RW 68
#define WO_AH 0
#define WO_AL (128 * RW)
#define WO_BH (2 * 128 * RW)
#define WO_BL (2 * 128 * RW + 64 * RW)
#define SM_WORDS (2 * 128 * RW + 2 * 64 * RW)
#define SM_TOTAL (SM_WORDS * 4)

__global__ __launch_bounds__(256, 2) void gemm_mma(const float* __restrict__ bias) {
    extern __shared__ uint32_t sw[];
    int t = threadIdx.x;
    int w = t >> 5, lane = t & 31;
    int row0 = blockIdx.x * 128;       // row tile fastest: B tile L2-reused 16x
    int col0 = blockIdx.y * 64;
    int ct = blockIdx.y;

    // ---- copies: global row (16 uint4) -> smem row (17 uint4, last = pad) ----
    {
        uint4* s4 = (uint4*)sw;
        const uint4* gah = (const uint4*)(g_Ah + (size_t)row0 * Dn);
        const uint4* gal = (const uint4*)(g_Al + (size_t)row0 * Dn);
#pragma unroll
        for (int i = 0; i < 8; i++) {
            int idx = t + i * 256;
            int r = idx >> 4, q = idx & 15;
            s4[(WO_AH / 4) + r * 17 + q] = gah[r * 16 + q];
            s4[(WO_AL / 4) + r * 17 + q] = gal[r * 16 + q];
        }
        const uint4* gbh = (const uint4*)(g_Bh + (size_t)col0 * Dn);
        const uint4* gbl = (const uint4*)(g_Bl + (size_t)col0 * Dn);
#pragma unroll
        for (int i = 0; i < 4; i++) {
            int idx = t + i * 256;
            int r = idx >> 4, q = idx & 15;
            s4[(WO_BH / 4) + r * 17 + q] = gbh[r * 16 + q];
            s4[(WO_BL / 4) + r * 17 + q] = gbl[r * 16 + q];
        }
    }
    __syncthreads();

    int wr = w & 3;                    // row group: 4 x 32 rows
    int wc = w >> 2;                   // col group: 2 x 32 cols
    int rq = lane >> 2;                // groupID
    int tig = lane & 3;                // threadID_in_group

    float acc[2][4][4];
#pragma unroll
    for (int mt = 0; mt < 2; mt++)
#pragma unroll
        for (int nt = 0; nt < 4; nt++)
#pragma unroll
            for (int i = 0; i < 4; i++) acc[mt][nt][i] = 0.f;

#pragma unroll
    for (int ks = 0; ks < 8; ks++) {
        int kw = ks * 8;
        uint32_t ah[2][4], al[2][4];
#pragma unroll
        for (int mt = 0; mt < 2; mt++) {
            int r0 = (wr * 32 + mt * 16 + rq) * RW + kw + tig;
            int r1 = r0 + 8 * RW;
            ah[mt][0] = sw[WO_AH + r0];
            ah[mt][1] = sw[WO_AH + r1];
            ah[mt][2] = sw[WO_AH + r0 + 4];
            ah[mt][3] = sw[WO_AH + r1 + 4];
            al[mt][0] = sw[WO_AL + r0];
            al[mt][1] = sw[WO_AL + r1];
            al[mt][2] = sw[WO_AL + r0 + 4];
            al[mt][3] = sw[WO_AL + r1 + 4];
        }
#pragma unroll
        for (int nt = 0; nt < 4; nt++) {
            int rb = (wc * 32 + nt * 8 + rq) * RW + kw + tig;
            uint32_t bh0 = sw[WO_BH + rb];
            uint32_t bh1 = sw[WO_BH + rb + 4];
            uint32_t bl0 = sw[WO_BL + rb];
            uint32_t bl1 = sw[WO_BL + rb + 4];
#pragma unroll
            for (int mt = 0; mt < 2; mt++) {
                mma16816(acc[mt][nt], ah[mt], bh0, bh1);  // Ah*Bh
                mma16816(acc[mt][nt], ah[mt], bl0, bl1);  // Ah*Bl
                mma16816(acc[mt][nt], al[mt], bh0, bh1);  // Al*Bh
            }
        }
    }
    __syncthreads();   // tiles dead; smem reused for row-sum combine

    // ---- epilogue: bias + fp16 store + per-row exp sums ----
    float rsp[4] = {0.f, 0.f, 0.f, 0.f};   // rows mt*16+rq, mt*16+8+rq
    float rsl[4] = {0.f, 0.f, 0.f, 0.f};
    int cq = tig * 2;
#pragma unroll
    for (int nt = 0; nt < 4; nt++) {
        int col = col0 + wc * 32 + nt * 8 + cq;
        if (col >= Cn) continue;
        float2 b2 = *(const float2*)&bias[col];
#pragma unroll
        for (int mt = 0; mt < 2; mt++) {
            int r = row0 + wr * 32 + mt * 16 + rq;
            float v00 = acc[mt][nt][0] + b2.x, v01 = acc[mt][nt][1] + b2.y;
            float v10 = acc[mt][nt][2] + b2.x, v11 = acc[mt][nt][3] + b2.y;
            *(__half2*)&g_wfh[(size_t)r * Cn + col] = __floats2half2_rn(v00, v01);
            *(__half2*)&g_wfh[(size_t)(r + 8) * Cn + col] = __floats2half2_rn(v10, v11);
            rsp[2 * mt]     += __expf(v00) + __expf(v01);
            rsp[2 * mt + 1] += __expf(v10) + __expf(v11);
            rsl[2 * mt]     += __expf(Sf * v00) + __expf(Sf * v01);
            rsl[2 * mt + 1] += __expf(Sf * v10) + __expf(Sf * v11);
        }
    }
    // reduce over the 4 lanes of each row group (tig bits)
#pragma unroll
    for (int j = 0; j < 4; j++) {
        rsp[j] += __shfl_xor_sync(0xffffffffu, rsp[j], 1);
        rsp[j] += __shfl_xor_sync(0xffffffffu, rsp[j], 2);
        rsl[j] += __shfl_xor_sync(0xffffffffu, rsl[j], 1);
        rsl[j] += __shfl_xor_sync(0xffffffffu, rsl[j], 2);
    }
    float* ssp = (float*)sw;           // [2][128]
    float* ssl = ((float*)sw) + 256;   // [2][128]
    if (tig == 0) {
#pragma unroll
        for (int j = 0; j < 4; j++) {
            int lrow = wr * 32 + (j >> 1) * 16 + (j & 1) * 8 + rq;
            ssp[wc * 128 + lrow] = rsp[j];
            ssl[wc * 128 + lrow] = rsl[j];
        }
    }
    __syncthreads();
    if (t < 128) {
        g_psp[(size_t)(row0 + t) * NCT + ct] = ssp[t] + ssp[128 + t];
        g_psl[(size_t)(row0 + t) * NCT + ct] = ssl[t] + ssl[128 + t];
    }
}

// ---------------------------------------------------------------------------
// Per-row: sum partials, fix label term, compute inv + loss. Block per row.
// ---------------------------------------------------------------------------
__global__ __launch_bounds__(256) void row_final(const int* __restrict__ labels) {
    int row = blockIdx.x;
    int t = threadIdx.x;
    __shared__ float red[512];
    float sp = 0.f, sl = 0.f;
    const float* pp = g_psp + (size_t)row * NCT;
    const float* pl = g_psl + (size_t)row * NCT;
    for (int i = t; i < NCT; i += 256) { sp += pp[i]; sl += pl[i]; }
    red[t] = sp; red[256 + t] = sl;
    __syncthreads();
#pragma unroll
    for (int s = 128; s; s >>= 1) {
        if (t < s) { red[t] += red[t + s]; red[256 + t] += red[256 + t + s]; }
        __syncthreads();
    }
    if (t == 0) {
        float spr = red[0], slr = red[256];
        float wl = __half2float(g_wfh[(size_t)row * Cn + labels[row]]);
        float cc = fminf(fmaxf(wl, -1.0f + EPSf), 1.0f - EPSf);
        float cosm = cc * COS_M - sqrtf(fmaxf(1.0f - cc * cc, 0.0f)) * SIN_M;
        float total = slr - __expf(Sf * wl) + __expf(Sf * cosm);
        g_loss[row] = logf(total) - Sf * cosm;
        g_inv[row] = 1.0f / spr;
    }
}

// ---------------------------------------------------------------------------
// Elementwise: pred = exp(wf_fp16) * inv[row]; streaming fp32 stores.
// ---------------------------------------------------------------------------
__global__ __launch_bounds__(256) void finalize(float* __restrict__ out) {
    int row = blockIdx.y;
    int i = blockIdx.x * 256 + threadIdx.x;         // group-of-4 index
    if (i >= Cn / 4) return;
    float inv = g_inv[row];
    const __half2* ph = (const __half2*)(g_wfh + (size_t)row * Cn + 4 * (size_t)i);
    __half2 h01 = ph[0], h23 = ph[1];
    float2 f01 = __half22float2(h01), f23 = __half22float2(h23);
    float4 v;
    v.x = __expf(f01.x) * inv;
    v.y = __expf(f01.y) * inv;
    v.z = __expf(f23.x) * inv;
    v.w = __expf(f23.y) * inv;
    st_cs_f4((float*)(out + (size_t)row * Cn) + 4 * (size_t)i, v);
}

// ---------------------------------------------------------------------------
__global__ __launch_bounds__(256) void loss_reduce(float* __restrict__ out) {
    __shared__ float red[256];
    int t = threadIdx.x;
    float s = 0.f;
    for (int i = t; i < Bn; i += 256) s += g_loss[i];
    red[t] = s; __syncthreads();
#pragma unroll
    for (int st = 128; st; st >>= 1) {
        if (t < st) red[t] += red[t + st];
        __syncthreads();
    }
    if (t == 0) out[(size_t)Bn * Cn] = red[0] / (float)Bn;
}

// ---------------------------------------------------------------------------
extern "C" void kernel_launch(void* const* d_in, const int* in_sizes, int n_in,
                              void* d_out, int out_size) {
    const float* x      = (const float*)d_in[0];
    const float* W      = (const float*)d_in[1];
    const float* bias   = (const float*)d_in[2];
    const int*   labels = (const int*)d_in[3];
    float* out = (float*)d_out;

    cudaFuncSetAttribute(gemm_mma, cudaFuncAttributeMaxDynamicSharedMemorySize,
                         SM_TOTAL);

    norm_split<<<Bn / 8, 256>>>(x, Bn, Bn, 0);
    norm_split<<<CPAD / 8, 256>>>(W, Cn, CPAD, 1);

    dim3 gg(NRT, NCT);   // row tile fastest -> each B tile loaded once
    gemm_mma<<<gg, 256, SM_TOTAL>>>(bias);

    row_final<<<Bn, 256>>>(labels);

    dim3 gf((Cn / 4 + 255) / 256, Bn);
    finalize<<<gf, 256>>>(out);

    loss_reduce<<<1, 256>>>(out);
}

// round 9
// speedup vs baseline: 1.5893x; 1.1362x over previous
#include <cuda_runtime.h>
#include <cuda_bf16.h>
#include <cuda_fp16.h>
#include <math.h>
#include <stdint.h>

// Problem constants
#define Bn 2048
#define Cn 50000
#define Dn 128
#define CPAD 50048            // Cn padded to multiple of 64
#define NCT (CPAD / 64)       // 782 column tiles
#define NRT (Bn / 128)        // 16 row tiles
#define Sf 20.0f
#define EPSf 1e-7f
#define COS_M 0.9950041652780258f
#define SIN_M 0.09983341664682815f

// fp16 scratch, plain row-major [row][128]
__device__ __align__(16) __half g_Ah[(size_t)Bn * Dn];
__device__ __align__(16) __half g_Al[(size_t)Bn * Dn];
__device__ __align__(16) __half g_Bh[(size_t)CPAD * Dn];
// fp16 wf (205 MB)
__device__ __half g_wfh[(size_t)Bn * Cn];
// Per-(row, coltile) partial sums (written unconditionally -> no zeroing)
__device__ float g_psp[(size_t)Bn * NCT];   // sum exp(wf)
__device__ float g_psl[(size_t)Bn * NCT];   // sum exp(20*wf)
__device__ float g_inv[Bn];
__device__ float g_loss[Bn];

// ---------------------------------------------------------------------------
__device__ __forceinline__ void mma16816(float* c, const uint32_t* a,
                                         uint32_t b0, uint32_t b1) {
    asm volatile(
        "mma.sync.aligned.m16n8k16.row.col.f32.f16.f16.f32 "
        "{%0,%1,%2,%3}, {%4,%5,%6,%7}, {%8,%9}, {%0,%1,%2,%3};"
        : "+f"(c[0]), "+f"(c[1]), "+f"(c[2]), "+f"(c[3])
        : "r"(a[0]), "r"(a[1]), "r"(a[2]), "r"(a[3]), "r"(b0), "r"(b1));
}
__device__ __forceinline__ void st_cs_f4(float* p, float4 v) {
    asm volatile("st.global.cs.v4.f32 [%0], {%1,%2,%3,%4};"
                 :: "l"(p), "f"(v.x), "f"(v.y), "f"(v.z), "f"(v.w) : "memory");
}

// ---------------------------------------------------------------------------
// Normalize + fp16 digits, plain row-major. One warp per row.
// which=0: write Ah + Al (two digits). which=1: write Bh only (one digit).
// Output arrays bound INSIDE device code (device symbols are invalid as
// host-side kernel args).
// ---------------------------------------------------------------------------
__global__ __launch_bounds__(256) void norm_split(const float* __restrict__ in,
                                                  int nrows, int npad,
                                                  int which) {
    int warp = (blockIdx.x * blockDim.x + threadIdx.x) >> 5;
    int lane = threadIdx.x & 31;
    if (warp >= npad) return;
    float4 v = make_float4(0.f, 0.f, 0.f, 0.f);
    if (warp < nrows) v = ((const float4*)(in + (size_t)warp * Dn))[lane];
    float ss = v.x * v.x + v.y * v.y + v.z * v.z + v.w * v.w;
#pragma unroll
    for (int o = 16; o; o >>= 1) ss += __shfl_xor_sync(0xffffffffu, ss, o);
    float sc = 1.0f / fmaxf(sqrtf(ss), 1e-12f);
    if (warp >= nrows) sc = 0.0f;
    v.x *= sc; v.y *= sc; v.z *= sc; v.w *= sc;

    __half2 h01 = __floats2half2_rn(v.x, v.y);
    __half2 h23 = __floats2half2_rn(v.z, v.w);
    size_t idx = (size_t)warp * Dn + 4 * lane;
    if (which) {
        uint2 hv;
        hv.x = *(uint32_t*)&h01; hv.y = *(uint32_t*)&h23;
        *(uint2*)(g_Bh + idx) = hv;
    } else {
        __half2 l01 = __floats2half2_rn(v.x - __half2float(h01.x),
                                        v.y - __half2float(h01.y));
        __half2 l23 = __floats2half2_rn(v.z - __half2float(h23.x),
                                        v.w - __half2float(h23.y));
        uint2 hv, lv;
        hv.x = *(uint32_t*)&h01; hv.y = *(uint32_t*)&h23;
        lv.x = *(uint32_t*)&l01; lv.y = *(uint32_t*)&l23;
        *(uint2*)(g_Ah + idx) = hv;
        *(uint2*)(g_Al + idx) = lv;
    }
}

// ---------------------------------------------------------------------------
// fp16 mma GEMM (2 products: Ah*Bh + Al*Bh) with fused exp-sum epilogue and
// fp16 wf store. CTA tile 128x64, 256 threads (8 warps of 32x32), K=128.
// SMEM as uint32 words, row stride 68 (64 data + 4 pad): 87040 bytes.
// ---------------------------------------------------------------------------
#define RW 68
#define WO_AH 0
#define WO_AL (128 * RW)
#define WO_BH (2 * 128 * RW)
#define SM_WORDS (2 * 128 * RW + 64 * RW)
#define SM_TOTAL (SM_WORDS * 4)

__global__ __launch_bounds__(256, 2) void gemm_mma(const float* __restrict__ bias) {
    extern __shared__ uint32_t sw[];
    int t = threadIdx.x;
    int w = t >> 5, lane = t & 31;
    int row0 = blockIdx.x * 128;       // row tile fastest: B tile L2-reused 16x
    int col0 = blockIdx.y * 64;
    int ct = blockIdx.y;

    // ---- copies: global row (16 uint4) -> smem row (17 uint4, last = pad) ----
    {
        uint4* s4 = (uint4*)sw;
        const uint4* gah = (const uint4*)(g_Ah + (size_t)row0 * Dn);
        const uint4* gal = (const uint4*)(g_Al + (size_t)row0 * Dn);
#pragma unroll
        for (int i = 0; i < 8; i++) {
            int idx = t + i * 256;
            int r = idx >> 4, q = idx & 15;
            s4[(WO_AH / 4) + r * 17 + q] = gah[r * 16 + q];
            s4[(WO_AL / 4) + r * 17 + q] = gal[r * 16 + q];
        }
        const uint4* gbh = (const uint4*)(g_Bh + (size_t)col0 * Dn);
#pragma unroll
        for (int i = 0; i < 4; i++) {
            int idx = t + i * 256;
            int r = idx >> 4, q = idx & 15;
            s4[(WO_BH / 4) + r * 17 + q] = gbh[r * 16 + q];
        }
    }
    __syncthreads();

    int wr = w & 3;                    // row group: 4 x 32 rows
    int wc = w >> 2;                   // col group: 2 x 32 cols
    int rq = lane >> 2;                // groupID
    int tig = lane & 3;                // threadID_in_group

    float acc[2][4][4];
#pragma unroll
    for (int mt = 0; mt < 2; mt++)
#pragma unroll
        for (int nt = 0; nt < 4; nt++)
#pragma unroll
            for (int i = 0; i < 4; i++) acc[mt][nt][i] = 0.f;

#pragma unroll
    for (int ks = 0; ks < 8; ks++) {
        int kw = ks * 8;
        uint32_t ah[2][4], al[2][4];
#pragma unroll
        for (int mt = 0; mt < 2; mt++) {
            int r0 = (wr * 32 + mt * 16 + rq) * RW + kw + tig;
            int r1 = r0 + 8 * RW;
            ah[mt][0] = sw[WO_AH + r0];
            ah[mt][1] = sw[WO_AH + r1];
            ah[mt][2] = sw[WO_AH + r0 + 4];
            ah[mt][3] = sw[WO_AH + r1 + 4];
            al[mt][0] = sw[WO_AL + r0];
            al[mt][1] = sw[WO_AL + r1];
            al[mt][2] = sw[WO_AL + r0 + 4];
            al[mt][3] = sw[WO_AL + r1 + 4];
        }
#pragma unroll
        for (int nt = 0; nt < 4; nt++) {
            int rb = (wc * 32 + nt * 8 + rq) * RW + kw + tig;
            uint32_t bh0 = sw[WO_BH + rb];
            uint32_t bh1 = sw[WO_BH + rb + 4];
#pragma unroll
            for (int mt = 0; mt < 2; mt++) {
                mma16816(acc[mt][nt], ah[mt], bh0, bh1);  // Ah*Bh
                mma16816(acc[mt][nt], al[mt], bh0, bh1);  // Al*Bh
            }
        }
    }
    __syncthreads();   // tiles dead; smem reused for row-sum combine

    // ---- epilogue: bias + fp16 store + per-row exp sums ----
    float rsp[4] = {0.f, 0.f, 0.f, 0.f};   // rows mt*16+rq, mt*16+8+rq
    float rsl[4] = {0.f, 0.f, 0.f, 0.f};
    int cq = tig * 2;
#pragma unroll
    for (int nt = 0; nt < 4; nt++) {
        int col = col0 + wc * 32 + nt * 8 + cq;
        if (col >= Cn) continue;
        float2 b2 = *(const float2*)&bias[col];
#pragma unroll
        for (int mt = 0; mt < 2; mt++) {
            int r = row0 + wr * 32 + mt * 16 + rq;
            float v00 = acc[mt][nt][0] + b2.x, v01 = acc[mt][nt][1] + b2.y;
            float v10 = acc[mt][nt][2] + b2.x, v11 = acc[mt][nt][3] + b2.y;
            *(__half2*)&g_wfh[(size_t)r * Cn + col] = __floats2half2_rn(v00, v01);
            *(__half2*)&g_wfh[(size_t)(r + 8) * Cn + col] = __floats2half2_rn(v10, v11);
            rsp[2 * mt]     += __expf(v00) + __expf(v01);
            rsp[2 * mt + 1] += __expf(v10) + __expf(v11);
            rsl[2 * mt]     += __expf(Sf * v00) + __expf(Sf * v01);
            rsl[2 * mt + 1] += __expf(Sf * v10) + __expf(Sf * v11);
        }
    }
    // reduce over the 4 lanes of each row group (tig bits)
#pragma unroll
    for (int j = 0; j < 4; j++) {
        rsp[j] += __shfl_xor_sync(0xffffffffu, rsp[j], 1);
        rsp[j] += __shfl_xor_sync(0xffffffffu, rsp[j], 2);
        rsl[j] += __shfl_xor_sync(0xffffffffu, rsl[j], 1);
        rsl[j] += __shfl_xor_sync(0xffffffffu, rsl[j], 2);
    }
    float* ssp = (float*)sw;           // [2][128]
    float* ssl = ((float*)sw) + 256;   // [2][128]
    if (tig == 0) {
#pragma unroll
        for (int j = 0; j < 4; j++) {
            int lrow = wr * 32 + (j >> 1) * 16 + (j & 1) * 8 + rq;
            ssp[wc * 128 + lrow] = rsp[j];
            ssl[wc * 128 + lrow] = rsl[j];
        }
    }
    __syncthreads();
    if (t < 128) {
        g_psp[(size_t)(row0 + t) * NCT + ct] = ssp[t] + ssp[128 + t];
        g_psl[(size_t)(row0 + t) * NCT + ct] = ssl[t] + ssl[128 + t];
    }
}

// ---------------------------------------------------------------------------
// Per-row: sum partials, fix label term, compute inv + loss. Block per row.
// ---------------------------------------------------------------------------
__global__ __launch_bounds__(256) void row_final(const int* __restrict__ labels) {
    int row = blockIdx.x;
    int t = threadIdx.x;
    __shared__ float red[512];
    float sp = 0.f, sl = 0.f;
    const float* pp = g_psp + (size_t)row * NCT;
    const float* pl = g_psl + (size_t)row * NCT;
    for (int i = t; i < NCT; i += 256) { sp += pp[i]; sl += pl[i]; }
    red[t] = sp; red[256 + t] = sl;
    __syncthreads();
#pragma unroll
    for (int s = 128; s; s >>= 1) {
        if (t < s) { red[t] += red[t + s]; red[256 + t] += red[256 + t + s]; }
        __syncthreads();
    }
    if (t == 0) {
        float spr = red[0], slr = red[256];
        float wl = __half2float(g_wfh[(size_t)row * Cn + labels[row]]);
        float cc = fminf(fmaxf(wl, -1.0f + EPSf), 1.0f - EPSf);
        float cosm = cc * COS_M - sqrtf(fmaxf(1.0f - cc * cc, 0.0f)) * SIN_M;
        float total = slr - __expf(Sf * wl) + __expf(Sf * cosm);
        g_loss[row] = logf(total) - Sf * cosm;
        g_inv[row] = 1.0f / spr;
    }
}

// ---------------------------------------------------------------------------
// Elementwise: pred = exp(wf_fp16) * inv[row]; streaming fp32 stores.
// ---------------------------------------------------------------------------
__global__ __launch_bounds__(256) void finalize(float* __restrict__ out) {
    int row = blockIdx.y;
    int i = blockIdx.x * 256 + threadIdx.x;         // group-of-4 index
    if (i >= Cn / 4) return;
    float inv = g_inv[row];
    const __half2* ph = (const __half2*)(g_wfh + (size_t)row * Cn + 4 * (size_t)i);
    __half2 h01 = ph[0], h23 = ph[1];
    float2 f01 = __half22float2(h01), f23 = __half22float2(h23);
    float4 v;
    v.x = __expf(f01.x) * inv;
    v.y = __expf(f01.y) * inv;
    v.z = __expf(f23.x) * inv;
    v.w = __expf(f23.y) * inv;
    st_cs_f4((float*)(out + (size_t)row * Cn) + 4 * (size_t)i, v);
}

// ---------------------------------------------------------------------------
__global__ __launch_bounds__(256) void loss_reduce(float* __restrict__ out) {
    __shared__ float red[256];
    int t = threadIdx.x;
    float s = 0.f;
    for (int i = t; i < Bn; i += 256) s += g_loss[i];
    red[t] = s; __syncthreads();
#pragma unroll
    for (int st = 128; st; st >>= 1) {
        if (t < st) red[t] += red[t + st];
        __syncthreads();
    }
    if (t == 0) out[(size_t)Bn * Cn] = red[0] / (float)Bn;
}

// ---------------------------------------------------------------------------
extern "C" void kernel_launch(void* const* d_in, const int* in_sizes, int n_in,
                              void* d_out, int out_size) {
    const float* x      = (const float*)d_in[0];
    const float* W      = (const float*)d_in[1];
    const float* bias   = (const float*)d_in[2];
    const int*   labels = (const int*)d_in[3];
    float* out = (float*)d_out;

    cudaFuncSetAttribute(gemm_mma, cudaFuncAttributeMaxDynamicSharedMemorySize,
                         SM_TOTAL);

    norm_split<<<Bn / 8, 256>>>(x, Bn, Bn, 0);
    norm_split<<<CPAD / 8, 256>>>(W, Cn, CPAD, 1);

    dim3 gg(NRT, NCT);   // row tile fastest -> each B tile loaded once
    gemm_mma<<<gg, 256, SM_TOTAL>>>(bias);

    row_final<<<Bn, 256>>>(labels);

    dim3 gf((Cn / 4 + 255) / 256, Bn);
    finalize<<<gf, 256>>>(out);

    loss_reduce<<<1, 256>>>(out);
}

// round 10
// speedup vs baseline: 2.0821x; 1.3101x over previous
#include <cuda_runtime.h>
#include <cuda_bf16.h>
#include <cuda_fp16.h>
#include <math.h>
#include <stdint.h>

// Problem constants
#define Bn 2048
#define Cn 50000
#define Dn 128
#define CPAD 50048            // Cn padded to multiple of 64
#define NCT (CPAD / 64)       // 782 column tiles
#define NRT (Bn / 128)        // 16 row tiles
#define Sf 20.0f
#define EPSf 1e-7f
#define COS_M 0.9950041652780258f
#define SIN_M 0.09983341664682815f

// fp16 scratch, plain row-major [row][128]
__device__ __align__(16) __half g_Ah[(size_t)Bn * Dn];
__device__ __align__(16) __half g_Bh[(size_t)CPAD * Dn];
// fp16 q = exp(wf) (205 MB)
__device__ __half g_q[(size_t)Bn * Cn];
// Per-(row, coltile) partial sums (written unconditionally -> no zeroing)
__device__ float g_psp[(size_t)Bn * NCT];   // sum exp(wf)
__device__ float g_psl[(size_t)Bn * NCT];   // sum exp(20*wf)
__device__ float g_wl[Bn];                  // wf at label column (fp32)
__device__ float g_inv[Bn];
__device__ float g_loss[Bn];

// ---------------------------------------------------------------------------
__device__ __forceinline__ void mma16816(float* c, const uint32_t* a,
                                         uint32_t b0, uint32_t b1) {
    asm volatile(
        "mma.sync.aligned.m16n8k16.row.col.f32.f16.f16.f32 "
        "{%0,%1,%2,%3}, {%4,%5,%6,%7}, {%8,%9}, {%0,%1,%2,%3};"
        : "+f"(c[0]), "+f"(c[1]), "+f"(c[2]), "+f"(c[3])
        : "r"(a[0]), "r"(a[1]), "r"(a[2]), "r"(a[3]), "r"(b0), "r"(b1));
}
__device__ __forceinline__ void st_cs_f4(float* p, float4 v) {
    asm volatile("st.global.cs.v4.f32 [%0], {%1,%2,%3,%4};"
                 :: "l"(p), "f"(v.x), "f"(v.y), "f"(v.z), "f"(v.w) : "memory");
}
__device__ __forceinline__ float pow20(float e) {
    float e2 = e * e;
    float e4 = e2 * e2;
    float e5 = e4 * e;
    float e10 = e5 * e5;
    return e10 * e10;
}

// ---------------------------------------------------------------------------
// Normalize -> single fp16 digit, plain row-major. One warp per row.
// Output array bound INSIDE device code (device symbols are invalid as
// host-side kernel args).
// ---------------------------------------------------------------------------
__global__ __launch_bounds__(256) void norm_quant(const float* __restrict__ in,
                                                  int nrows, int npad,
                                                  int which) {
    int warp = (blockIdx.x * blockDim.x + threadIdx.x) >> 5;
    int lane = threadIdx.x & 31;
    if (warp >= npad) return;
    float4 v = make_float4(0.f, 0.f, 0.f, 0.f);
    if (warp < nrows) v = ((const float4*)(in + (size_t)warp * Dn))[lane];
    float ss = v.x * v.x + v.y * v.y + v.z * v.z + v.w * v.w;
#pragma unroll
    for (int o = 16; o; o >>= 1) ss += __shfl_xor_sync(0xffffffffu, ss, o);
    float sc = 1.0f / fmaxf(sqrtf(ss), 1e-12f);
    if (warp >= nrows) sc = 0.0f;

    __half2 h01 = __floats2half2_rn(v.x * sc, v.y * sc);
    __half2 h23 = __floats2half2_rn(v.z * sc, v.w * sc);
    __half* dst = which ? g_Bh : g_Ah;
    size_t idx = (size_t)warp * Dn + 4 * lane;
    uint2 hv;
    hv.x = *(uint32_t*)&h01; hv.y = *(uint32_t*)&h23;
    *(uint2*)(dst + idx) = hv;
}

// ---------------------------------------------------------------------------
// fp16 mma GEMM (single product) with fused exp epilogue:
//   e = exp(wf); store fp16(e); sp += e; sl += e^20; capture wl at label.
// CTA tile 128x64, 256 threads (8 warps of 32x32), K=128.
// SMEM as uint32 words, row stride 68 (64 data + 4 pad): 52224 bytes.
// ---------------------------------------------------------------------------
#define RW 68
#define WO_AH 0
#define WO_BH (128 * RW)
#define SM_WORDS (128 * RW + 64 * RW)
#define SM_TOTAL (SM_WORDS * 4)

__global__ __launch_bounds__(256, 2) void gemm_mma(const float* __restrict__ bias,
                                                   const int* __restrict__ labels) {
    extern __shared__ uint32_t sw[];
    int t = threadIdx.x;
    int w = t >> 5, lane = t & 31;
    int row0 = blockIdx.x * 128;       // row tile fastest: B tile L2-reused 16x
    int col0 = blockIdx.y * 64;
    int ct = blockIdx.y;

    // ---- copies: global row (16 uint4) -> smem row (17 uint4, last = pad) ----
    {
        uint4* s4 = (uint4*)sw;
        const uint4* gah = (const uint4*)(g_Ah + (size_t)row0 * Dn);
#pragma unroll
        for (int i = 0; i < 8; i++) {
            int idx = t + i * 256;
            int r = idx >> 4, q = idx & 15;
            s4[(WO_AH / 4) + r * 17 + q] = gah[r * 16 + q];
        }
        const uint4* gbh = (const uint4*)(g_Bh + (size_t)col0 * Dn);
#pragma unroll
        for (int i = 0; i < 4; i++) {
            int idx = t + i * 256;
            int r = idx >> 4, q = idx & 15;
            s4[(WO_BH / 4) + r * 17 + q] = gbh[r * 16 + q];
        }
    }
    __syncthreads();

    int wr = w & 3;                    // row group: 4 x 32 rows
    int wc = w >> 2;                   // col group: 2 x 32 cols
    int rq = lane >> 2;                // groupID
    int tig = lane & 3;                // threadID_in_group

    float acc[2][4][4];
#pragma unroll
    for (int mt = 0; mt < 2; mt++)
#pragma unroll
        for (int nt = 0; nt < 4; nt++)
#pragma unroll
            for (int i = 0; i < 4; i++) acc[mt][nt][i] = 0.f;

#pragma unroll
    for (int ks = 0; ks < 8; ks++) {
        int kw = ks * 8;
        uint32_t ah[2][4];
#pragma unroll
        for (int mt = 0; mt < 2; mt++) {
            int r0 = (wr * 32 + mt * 16 + rq) * RW + kw + tig;
            int r1 = r0 + 8 * RW;
            ah[mt][0] = sw[WO_AH + r0];
            ah[mt][1] = sw[WO_AH + r1];
            ah[mt][2] = sw[WO_AH + r0 + 4];
            ah[mt][3] = sw[WO_AH + r1 + 4];
        }
#pragma unroll
        for (int nt = 0; nt < 4; nt++) {
            int rb = (wc * 32 + nt * 8 + rq) * RW + kw + tig;
            uint32_t bh0 = sw[WO_BH + rb];
            uint32_t bh1 = sw[WO_BH + rb + 4];
#pragma unroll
            for (int mt = 0; mt < 2; mt++)
                mma16816(acc[mt][nt], ah[mt], bh0, bh1);
        }
    }
    __syncthreads();   // tiles dead; smem reused for row-sum combine

    // ---- epilogue ----
    float rsp[4] = {0.f, 0.f, 0.f, 0.f};   // rows mt*16+rq, mt*16+8+rq
    float rsl[4] = {0.f, 0.f, 0.f, 0.f};
    int cq = tig * 2;
    int r0g = row0 + wr * 32 + rq;          // mt=0 row
    int lbl[4];                             // labels for rows r0g, +8, +16, +24
    lbl[0] = labels[r0g];
    lbl[1] = labels[r0g + 8];
    lbl[2] = labels[r0g + 16];
    lbl[3] = labels[r0g + 24];
#pragma unroll
    for (int nt = 0; nt < 4; nt++) {
        int col = col0 + wc * 32 + nt * 8 + cq;
        if (col >= Cn) continue;
        float2 b2 = *(const float2*)&bias[col];
#pragma unroll
        for (int mt = 0; mt < 2; mt++) {
            int r = r0g + mt * 16;
            float v00 = acc[mt][nt][0] + b2.x, v01 = acc[mt][nt][1] + b2.y;
            float v10 = acc[mt][nt][2] + b2.x, v11 = acc[mt][nt][3] + b2.y;
            // label capture (rare predicated stores, fp32-precise)
            if (lbl[2 * mt] == col)     g_wl[r] = v00;
            if (lbl[2 * mt] == col + 1) g_wl[r] = v01;
            if (lbl[2 * mt + 1] == col)     g_wl[r + 8] = v10;
            if (lbl[2 * mt + 1] == col + 1) g_wl[r + 8] = v11;
            float e00 = __expf(v00), e01 = __expf(v01);
            float e10 = __expf(v10), e11 = __expf(v11);
            *(__half2*)&g_q[(size_t)r * Cn + col] = __floats2half2_rn(e00, e01);
            *(__half2*)&g_q[(size_t)(r + 8) * Cn + col] = __floats2half2_rn(e10, e11);
            rsp[2 * mt]     += e00 + e01;
            rsp[2 * mt + 1] += e10 + e11;
            rsl[2 * mt]     += pow20(e00) + pow20(e01);
            rsl[2 * mt + 1] += pow20(e10) + pow20(e11);
        }
    }
    // reduce over the 4 lanes of each row group (tig bits)
#pragma unroll
    for (int j = 0; j < 4; j++) {
        rsp[j] += __shfl_xor_sync(0xffffffffu, rsp[j], 1);
        rsp[j] += __shfl_xor_sync(0xffffffffu, rsp[j], 2);
        rsl[j] += __shfl_xor_sync(0xffffffffu, rsl[j], 1);
        rsl[j] += __shfl_xor_sync(0xffffffffu, rsl[j], 2);
    }
    float* ssp = (float*)sw;           // [2][128]
    float* ssl = ((float*)sw) + 256;   // [2][128]
    if (tig == 0) {
#pragma unroll
        for (int j = 0; j < 4; j++) {
            int lrow = wr * 32 + (j >> 1) * 16 + (j & 1) * 8 + rq;
            ssp[wc * 128 + lrow] = rsp[j];
            ssl[wc * 128 + lrow] = rsl[j];
        }
    }
    __syncthreads();
    if (t < 128) {
        g_psp[(size_t)(row0 + t) * NCT + ct] = ssp[t] + ssp[128 + t];
        g_psl[(size_t)(row0 + t) * NCT + ct] = ssl[t] + ssl[128 + t];
    }
}

// ---------------------------------------------------------------------------
// Per-row: sum partials, fix label term, compute inv + loss. Block per row.
// ---------------------------------------------------------------------------
__global__ __launch_bounds__(256) void row_final(const int* __restrict__ labels) {
    int row = blockIdx.x;
    int t = threadIdx.x;
    __shared__ float red[512];
    float sp = 0.f, sl = 0.f;
    const float* pp = g_psp + (size_t)row * NCT;
    const float* pl = g_psl + (size_t)row * NCT;
    for (int i = t; i < NCT; i += 256) { sp += pp[i]; sl += pl[i]; }
    red[t] = sp; red[256 + t] = sl;
    __syncthreads();
#pragma unroll
    for (int s = 128; s; s >>= 1) {
        if (t < s) { red[t] += red[t + s]; red[256 + t] += red[256 + t + s]; }
        __syncthreads();
    }
    if (t == 0) {
        float spr = red[0], slr = red[256];
        float wl = g_wl[row];
        float cc = fminf(fmaxf(wl, -1.0f + EPSf), 1.0f - EPSf);
        float cosm = cc * COS_M - sqrtf(fmaxf(1.0f - cc * cc, 0.0f)) * SIN_M;
        float total = slr - __expf(Sf * wl) + __expf(Sf * cosm);
        g_loss[row] = logf(total) - Sf * cosm;
        g_inv[row] = 1.0f / spr;
    }
}

// ---------------------------------------------------------------------------
// Elementwise: pred = q * inv[row]; no exp; streaming fp32 stores.
// ---------------------------------------------------------------------------
__global__ __launch_bounds__(256) void finalize(float* __restrict__ out) {
    int row = blockIdx.y;
    int i = blockIdx.x * 256 + threadIdx.x;         // group-of-4 index
    if (i >= Cn / 4) return;
    float inv = g_inv[row];
    const __half2* ph = (const __half2*)(g_q + (size_t)row * Cn + 4 * (size_t)i);
    __half2 h01 = ph[0], h23 = ph[1];
    float2 f01 = __half22float2(h01), f23 = __half22float2(h23);
    float4 v;
    v.x = f01.x * inv;
    v.y = f01.y * inv;
    v.z = f23.x * inv;
    v.w = f23.y * inv;
    st_cs_f4((float*)(out + (size_t)row * Cn) + 4 * (size_t)i, v);
}

// ---------------------------------------------------------------------------
__global__ __launch_bounds__(256) void loss_reduce(float* __restrict__ out) {
    __shared__ float red[256];
    int t = threadIdx.x;
    float s = 0.f;
    for (int i = t; i < Bn; i += 256) s += g_loss[i];
    red[t] = s; __syncthreads();
#pragma unroll
    for (int st = 128; st; st >>= 1) {
        if (t < st) red[t] += red[t + st];
        __syncthreads();
    }
    if (t == 0) out[(size_t)Bn * Cn] = red[0] / (float)Bn;
}

// ---------------------------------------------------------------------------
extern "C" void kernel_launch(void* const* d_in, const int* in_sizes, int n_in,
                              void* d_out, int out_size) {
    const float* x      = (const float*)d_in[0];
    const float* W      = (const float*)d_in[1];
    const float* bias   = (const float*)d_in[2];
    const int*   labels = (const int*)d_in[3];
    float* out = (float*)d_out;

    cudaFuncSetAttribute(gemm_mma, cudaFuncAttributeMaxDynamicSharedMemorySize,
                         SM_TOTAL);

    norm_quant<<<Bn / 8, 256>>>(x, Bn, Bn, 0);
    norm_quant<<<CPAD / 8, 256>>>(W, Cn, CPAD, 1);

    dim3 gg(NRT, NCT);   // row tile fastest -> each B tile loaded once
    gemm_mma<<<gg, 256, SM_TOTAL>>>(bias, labels);

    row_final<<<Bn, 256>>>(labels);

    dim3 gf((Cn / 4 + 255) / 256, Bn);
    finalize<<<gf, 256>>>(out);

    loss_reduce<<<1, 256>>>(out);
}

// round 12
// speedup vs baseline: 2.2832x; 1.0966x over previous
#include <cuda_runtime.h>
#include <cuda_bf16.h>
#include <cuda_fp16.h>
#include <math.h>
#include <stdint.h>

// Problem constants
#define Bn 2048
#define Cn 50000
#define Dn 128
#define CPAD 50048            // Cn padded to multiple of 64
#define NCT (CPAD / 64)       // 782 column tiles
#define NRT (Bn / 128)        // 16 row tiles
#define Sf 20.0f
#define EPSf 1e-7f
#define COS_M 0.9950041652780258f
#define SIN_M 0.09983341664682815f

// fp16 scratch, plain row-major [row][128]
__device__ __align__(16) __half g_Ah[(size_t)Bn * Dn];
__device__ __align__(16) __half g_Bh[(size_t)CPAD * Dn];
// fp16 q = exp(wf) (205 MB)
__device__ __half g_q[(size_t)Bn * Cn];
// Per-(row, coltile) partial sums (written unconditionally -> no zeroing)
__device__ float g_psp[(size_t)Bn * NCT];   // sum exp(wf)
__device__ float g_psl[(size_t)Bn * NCT];   // sum exp(20*wf)
__device__ float g_wl[Bn];                  // wf at label column (fp32)
__device__ float g_inv[Bn];
__device__ float g_loss[Bn];

// ---------------------------------------------------------------------------
// fp16-accumulator HMMA: D(f16x2 x2) = A(f16 x4) * B(f16 x2) + C
// C fragment coordinates identical to the f32 variant: reg0 = (row g, cols
// 2*tig, 2*tig+1), reg1 = same cols at row g+8.
// ---------------------------------------------------------------------------
__device__ __forceinline__ void mma16816h(uint32_t* c, const uint32_t* a,
                                          uint32_t b0, uint32_t b1) {
    asm volatile(
        "mma.sync.aligned.m16n8k16.row.col.f16.f16.f16.f16 "
        "{%0,%1}, {%2,%3,%4,%5}, {%6,%7}, {%0,%1};"
        : "+r"(c[0]), "+r"(c[1])
        : "r"(a[0]), "r"(a[1]), "r"(a[2]), "r"(a[3]), "r"(b0), "r"(b1));
}
__device__ __forceinline__ void st_cs_f4(float* p, float4 v) {
    asm volatile("st.global.cs.v4.f32 [%0], {%1,%2,%3,%4};"
                 :: "l"(p), "f"(v.x), "f"(v.y), "f"(v.z), "f"(v.w) : "memory");
}
__device__ __forceinline__ float pow20(float e) {
    float e2 = e * e;
    float e4 = e2 * e2;
    float e5 = e4 * e;
    float e10 = e5 * e5;
    return e10 * e10;
}

// ---------------------------------------------------------------------------
// Normalize -> single fp16 digit, plain row-major. One warp per row.
// Output array bound INSIDE device code (device symbols are invalid as
// host-side kernel args).
// ---------------------------------------------------------------------------
__global__ __launch_bounds__(256) void norm_quant(const float* __restrict__ in,
                                                  int nrows, int npad,
                                                  int which) {
    int warp = (blockIdx.x * blockDim.x + threadIdx.x) >> 5;
    int lane = threadIdx.x & 31;
    if (warp >= npad) return;
    float4 v = make_float4(0.f, 0.f, 0.f, 0.f);
    if (warp < nrows) v = ((const float4*)(in + (size_t)warp * Dn))[lane];
    float ss = v.x * v.x + v.y * v.y + v.z * v.z + v.w * v.w;
#pragma unroll
    for (int o = 16; o; o >>= 1) ss += __shfl_xor_sync(0xffffffffu, ss, o);
    float sc = 1.0f / fmaxf(sqrtf(ss), 1e-12f);
    if (warp >= nrows) sc = 0.0f;

    __half2 h01 = __floats2half2_rn(v.x * sc, v.y * sc);
    __half2 h23 = __floats2half2_rn(v.z * sc, v.w * sc);
    __half* dst = which ? g_Bh : g_Ah;
    size_t idx = (size_t)warp * Dn + 4 * lane;
    uint2 hv;
    hv.x = *(uint32_t*)&h01; hv.y = *(uint32_t*)&h23;
    *(uint2*)(dst + idx) = hv;
}

// ---------------------------------------------------------------------------
// fp16 mma GEMM (fp16 accumulators) with fused exp epilogue:
//   e = exp(wf); store fp16(e); sp += e; sl += e^20; capture wl at label.
// CTA tile 128x64, 256 threads (8 warps of 32x32), K=128.
// SMEM as uint32 words, row stride 68 (64 data + 4 pad): 52224 bytes.
// ---------------------------------------------------------------------------
#define RW 68
#define WO_AH 0
#define WO_BH (128 * RW)
#define SM_WORDS (128 * RW + 64 * RW)
#define SM_TOTAL (SM_WORDS * 4)

__global__ __launch_bounds__(256, 3) void gemm_mma(const float* __restrict__ bias,
                                                   const int* __restrict__ labels) {
    extern __shared__ uint32_t sw[];
    int t = threadIdx.x;
    int w = t >> 5, lane = t & 31;
    int row0 = blockIdx.x * 128;       // row tile fastest: B tile L2-reused 16x
    int col0 = blockIdx.y * 64;
    int ct = blockIdx.y;

    // ---- copies: global row (16 uint4) -> smem row (17 uint4, last = pad) ----
    {
        uint4* s4 = (uint4*)sw;
        const uint4* gah = (const uint4*)(g_Ah + (size_t)row0 * Dn);
#pragma unroll
        for (int i = 0; i < 8; i++) {
            int idx = t + i * 256;
            int r = idx >> 4, q = idx & 15;
            s4[(WO_AH / 4) + r * 17 + q] = gah[r * 16 + q];
        }
        const uint4* gbh = (const uint4*)(g_Bh + (size_t)col0 * Dn);
#pragma unroll
        for (int i = 0; i < 4; i++) {
            int idx = t + i * 256;
            int r = idx >> 4, q = idx & 15;
            s4[(WO_BH / 4) + r * 17 + q] = gbh[r * 16 + q];
        }
    }
    __syncthreads();

    int wr = w & 3;                    // row group: 4 x 32 rows
    int wc = w >> 2;                   // col group: 2 x 32 cols
    int rq = lane >> 2;                // groupID
    int tig = lane & 3;                // threadID_in_group

    uint32_t acc[2][4][2];
#pragma unroll
    for (int mt = 0; mt < 2; mt++)
#pragma unroll
        for (int nt = 0; nt < 4; nt++) { acc[mt][nt][0] = 0u; acc[mt][nt][1] = 0u; }

#pragma unroll
    for (int ks = 0; ks < 8; ks++) {
        int kw = ks * 8;
        uint32_t ah[2][4];
#pragma unroll
        for (int mt = 0; mt < 2; mt++) {
            int r0 = (wr * 32 + mt * 16 + rq) * RW + kw + tig;
            int r1 = r0 + 8 * RW;
            ah[mt][0] = sw[WO_AH + r0];
            ah[mt][1] = sw[WO_AH + r1];
            ah[mt][2] = sw[WO_AH + r0 + 4];
            ah[mt][3] = sw[WO_AH + r1 + 4];
        }
#pragma unroll
        for (int nt = 0; nt < 4; nt++) {
            int rb = (wc * 32 + nt * 8 + rq) * RW + kw + tig;
            uint32_t bh0 = sw[WO_BH + rb];
            uint32_t bh1 = sw[WO_BH + rb + 4];
#pragma unroll
            for (int mt = 0; mt < 2; mt++)
                mma16816h(acc[mt][nt], ah[mt], bh0, bh1);
        }
    }
    __syncthreads();   // tiles dead; smem reused for row-sum combine

    // ---- epilogue ----
    float rsp[4] = {0.f, 0.f, 0.f, 0.f};   // rows mt*16+rq, mt*16+8+rq
    float rsl[4] = {0.f, 0.f, 0.f, 0.f};
    int cq = tig * 2;
    int r0g = row0 + wr * 32 + rq;          // mt=0 row
    int lbl[4];                             // labels for rows r0g, +8, +16, +24
    lbl[0] = labels[r0g];
    lbl[1] = labels[r0g + 8];
    lbl[2] = labels[r0g + 16];
    lbl[3] = labels[r0g + 24];
#pragma unroll
    for (int nt = 0; nt < 4; nt++) {
        int col = col0 + wc * 32 + nt * 8 + cq;
        if (col >= Cn) continue;
        float2 b2 = *(const float2*)&bias[col];
#pragma unroll
        for (int mt = 0; mt < 2; mt++) {
            int r = r0g + mt * 16;
            float2 f0 = __half22float2(*(__half2*)&acc[mt][nt][0]);
            float2 f1 = __half22float2(*(__half2*)&acc[mt][nt][1]);
            float v00 = f0.x + b2.x, v01 = f0.y + b2.y;
            float v10 = f1.x + b2.x, v11 = f1.y + b2.y;
            // label capture (rare predicated stores, fp32-precise)
            if (lbl[2 * mt] == col)     g_wl[r] = v00;
            if (lbl[2 * mt] == col + 1) g_wl[r] = v01;
            if (lbl[2 * mt + 1] == col)     g_wl[r + 8] = v10;
            if (lbl[2 * mt + 1] == col + 1) g_wl[r + 8] = v11;
            float e00 = __expf(v00), e01 = __expf(v01);
            float e10 = __expf(v10), e11 = __expf(v11);
            *(__half2*)&g_q[(size_t)r * Cn + col] = __floats2half2_rn(e00, e01);
            *(__half2*)&g_q[(size_t)(r + 8) * Cn + col] = __floats2half2_rn(e10, e11);
            rsp[2 * mt]     += e00 + e01;
            rsp[2 * mt + 1] += e10 + e11;
            rsl[2 * mt]     += pow20(e00) + pow20(e01);
            rsl[2 * mt + 1] += pow20(e10) + pow20(e11);
        }
    }
    // reduce over the 4 lanes of each row group (tig bits)
#pragma unroll
    for (int j = 0; j < 4; j++) {
        rsp[j] += __shfl_xor_sync(0xffffffffu, rsp[j], 1);
        rsp[j] += __shfl_xor_sync(0xffffffffu, rsp[j], 2);
        rsl[j] += __shfl_xor_sync(0xffffffffu, rsl[j], 1);
        rsl[j] += __shfl_xor_sync(0xffffffffu, rsl[j], 2);
    }
    float* ssp = (float*)sw;           // [2][128]
    float* ssl = ((float*)sw) + 256;   // [2][128]
    if (tig == 0) {
#pragma unroll
        for (int j = 0; j < 4; j++) {
            int lrow = wr * 32 + (j >> 1) * 16 + (j & 1) * 8 + rq;
            ssp[wc * 128 + lrow] = rsp[j];
            ssl[wc * 128 + lrow] = rsl[j];
        }
    }
    __syncthreads();
    if (t < 128) {
        g_psp[(size_t)(row0 + t) * NCT + ct] = ssp[t] + ssp[128 + t];
        g_psl[(size_t)(row0 + t) * NCT + ct] = ssl[t] + ssl[128 + t];
    }
}

// ---------------------------------------------------------------------------
// Per-row: sum partials, fix label term, compute inv + loss. Block per row.
// ---------------------------------------------------------------------------
__global__ __launch_bounds__(256) void row_final(const int* __restrict__ labels) {
    int row = blockIdx.x;
    int t = threadIdx.x;
    __shared__ float red[512];
    float sp = 0.f, sl = 0.f;
    const float* pp = g_psp + (size_t)row * NCT;
    const float* pl = g_psl + (size_t)row * NCT;
    for (int i = t; i < NCT; i += 256) { sp += pp[i]; sl += pl[i]; }
    red[t] = sp; red[256 + t] = sl;
    __syncthreads();
#pragma unroll
    for (int s = 128; s; s >>= 1) {
        if (t < s) { red[t] += red[t + s]; red[256 + t] += red[256 + t + s]; }
        __syncthreads();
    }
    if (t == 0) {
        float spr = red[0], slr = red[256];
        float wl = g_wl[row];
        float cc = fminf(fmaxf(wl, -1.0f + EPSf), 1.0f - EPSf);
        float cosm = cc * COS_M - sqrtf(fmaxf(1.0f - cc * cc, 0.0f)) * SIN_M;
        float total = slr - __expf(Sf * wl) + __expf(Sf * cosm);
        g_loss[row] = logf(total) - Sf * cosm;
        g_inv[row] = 1.0f / spr;
    }
}

// ---------------------------------------------------------------------------
// Elementwise: pred = q * inv[row]; no exp; streaming fp32 stores.
// ---------------------------------------------------------------------------
__global__ __launch_bounds__(256) void finalize(float* __restrict__ out) {
    int row = blockIdx.y;
    int i = blockIdx.x * 256 + threadIdx.x;         // group-of-4 index
    if (i >= Cn / 4) return;
    float inv = g_inv[row];
    const __half2* ph = (const __half2*)(g_q + (size_t)row * Cn + 4 * (size_t)i);
    __half2 h01 = ph[0], h23 = ph[1];
    float2 f01 = __half22float2(h01), f23 = __half22float2(h23);
    float4 v;
    v.x = f01.x * inv;
    v.y = f01.y * inv;
    v.z = f23.x * inv;
    v.w = f23.y * inv;
    st_cs_f4((float*)(out + (size_t)row * Cn) + 4 * (size_t)i, v);
}

// ---------------------------------------------------------------------------
__global__ __launch_bounds__(256) void loss_reduce(float* __restrict__ out) {
    __shared__ float red[256];
    int t = threadIdx.x;
    float s = 0.f;
    for (int i = t; i < Bn; i += 256) s += g_loss[i];
    red[t] = s; __syncthreads();
#pragma unroll
    for (int st = 128; st; st >>= 1) {
        if (t < st) red[t] += red[t + st];
        __syncthreads();
    }
    if (t == 0) out[(size_t)Bn * Cn] = red[0] / (float)Bn;
}

// ---------------------------------------------------------------------------
extern "C" void kernel_launch(void* const* d_in, const int* in_sizes, int n_in,
                              void* d_out, int out_size) {
    const float* x      = (const float*)d_in[0];
    const float* W      = (const float*)d_in[1];
    const float* bias   = (const float*)d_in[2];
    const int*   labels = (const int*)d_in[3];
    float* out = (float*)d_out;

    cudaFuncSetAttribute(gemm_mma, cudaFuncAttributeMaxDynamicSharedMemorySize,
                         SM_TOTAL);

    norm_quant<<<Bn / 8, 256>>>(x, Bn, Bn, 0);
    norm_quant<<<CPAD / 8, 256>>>(W, Cn, CPAD, 1);

    dim3 gg(NRT, NCT);   // row tile fastest -> each B tile loaded once
    gemm_mma<<<gg, 256, SM_TOTAL>>>(bias, labels);

    row_final<<<Bn, 256>>>(labels);

    dim3 gf((Cn / 4 + 255) / 256, Bn);
    finalize<<<gf, 256>>>(out);

    loss_reduce<<<1, 256>>>(out);
}

// round 14
// speedup vs baseline: 2.3663x; 1.0364x over previous
#include <cuda_runtime.h>
#include <cuda_bf16.h>
#include <cuda_fp16.h>
#include <math.h>
#include <stdint.h>

// Problem constants
#define Bn 2048
#define Cn 50000
#define Dn 128
#define CPAD 50048            // Cn padded: 128 * 391 exactly
#define NCT 391               // 128-wide column tiles
#define NRT (Bn / 128)        // 16 row tiles
#define Sf 20.0f
#define EPSf 1e-7f
#define COS_M 0.9950041652780258f
#define SIN_M 0.09983341664682815f

// fp16 scratch, plain row-major [row][128]
__device__ __align__(16) __half g_Ah[(size_t)Bn * Dn];
__device__ __align__(16) __half g_Bh[(size_t)CPAD * Dn];
// fp16 q = exp(wf) (205 MB)
__device__ __half g_q[(size_t)Bn * Cn];
// Per-(row, coltile) partial sums (written unconditionally -> no zeroing)
__device__ float g_psp[(size_t)Bn * NCT];   // sum exp(wf)
__device__ float g_psl[(size_t)Bn * NCT];   // sum exp(20*wf)
__device__ float g_wl[Bn];                  // wf at label column (fp32)
__device__ float g_inv[Bn];
__device__ float g_loss[Bn];

// ---------------------------------------------------------------------------
__device__ __forceinline__ uint32_t smem_u32(const void* p) {
    uint32_t a;
    asm("{ .reg .u64 t; cvta.to.shared.u64 t, %1; cvt.u32.u64 %0, t; }"
        : "=r"(a) : "l"(p));
    return a;
}
__device__ __forceinline__ void ldsm4(uint32_t& r0, uint32_t& r1, uint32_t& r2,
                                      uint32_t& r3, uint32_t addr) {
    asm volatile("ldmatrix.sync.aligned.m8n8.x4.shared.b16 {%0,%1,%2,%3}, [%4];"
                 : "=r"(r0), "=r"(r1), "=r"(r2), "=r"(r3) : "r"(addr));
}
// fp16-accumulator HMMA
__device__ __forceinline__ void mma16816h(uint32_t* c, const uint32_t* a,
                                          uint32_t b0, uint32_t b1) {
    asm volatile(
        "mma.sync.aligned.m16n8k16.row.col.f16.f16.f16.f16 "
        "{%0,%1}, {%2,%3,%4,%5}, {%6,%7}, {%0,%1};"
        : "+r"(c[0]), "+r"(c[1])
        : "r"(a[0]), "r"(a[1]), "r"(a[2]), "r"(a[3]), "r"(b0), "r"(b1));
}
__device__ __forceinline__ void st_cs_f4(float* p, float4 v) {
    asm volatile("st.global.cs.v4.f32 [%0], {%1,%2,%3,%4};"
                 :: "l"(p), "f"(v.x), "f"(v.y), "f"(v.z), "f"(v.w) : "memory");
}
__device__ __forceinline__ float pow20(float e) {
    float e2 = e * e;
    float e4 = e2 * e2;
    float e5 = e4 * e;
    float e10 = e5 * e5;
    return e10 * e10;
}

// ---------------------------------------------------------------------------
// Normalize -> single fp16 digit, plain row-major. One warp per row.
// Output array bound INSIDE device code (device symbols are invalid as
// host-side kernel args).
// ---------------------------------------------------------------------------
__global__ __launch_bounds__(256) void norm_quant(const float* __restrict__ in,
                                                  int nrows, int npad,
                                                  int which) {
    int warp = (blockIdx.x * blockDim.x + threadIdx.x) >> 5;
    int lane = threadIdx.x & 31;
    if (warp >= npad) return;
    float4 v = make_float4(0.f, 0.f, 0.f, 0.f);
    if (warp < nrows) v = ((const float4*)(in + (size_t)warp * Dn))[lane];
    float ss = v.x * v.x + v.y * v.y + v.z * v.z + v.w * v.w;
#pragma unroll
    for (int o = 16; o; o >>= 1) ss += __shfl_xor_sync(0xffffffffu, ss, o);
    float sc = 1.0f / fmaxf(sqrtf(ss), 1e-12f);
    if (warp >= nrows) sc = 0.0f;

    __half2 h01 = __floats2half2_rn(v.x * sc, v.y * sc);
    __half2 h23 = __floats2half2_rn(v.z * sc, v.w * sc);
    __half* dst = which ? g_Bh : g_Ah;
    size_t idx = (size_t)warp * Dn + 4 * lane;
    uint2 hv;
    hv.x = *(uint32_t*)&h01; hv.y = *(uint32_t*)&h23;
    *(uint2*)(dst + idx) = hv;
}

// ---------------------------------------------------------------------------
// fp16 mma GEMM (fp16 acc, ldmatrix fragments) with fused exp epilogue.
// CTA tile 128x128, 256 threads (8 warps of 32x64), K=128.
// SMEM as uint32 words, row stride 68 (64 data + 4 pad): 69632 bytes.
// ---------------------------------------------------------------------------
#define RW 68
#define WO_AH 0
#define WO_BH (128 * RW)
#define SM_WORDS (256 * RW)
#define SM_TOTAL (SM_WORDS * 4)

__global__ __launch_bounds__(256, 3) void gemm_mma(const float* __restrict__ bias,
                                                   const int* __restrict__ labels) {
    extern __shared__ uint32_t sw[];
    uint32_t sb = smem_u32(sw);
    int t = threadIdx.x;
    int w = t >> 5, lane = t & 31;
    int row0 = blockIdx.x * 128;       // row tile fastest: B tile L2-reused 16x
    int col0 = blockIdx.y * 128;
    int ct = blockIdx.y;

    // ---- copies: global row (16 uint4) -> smem row (17 uint4, last = pad) ----
    {
        uint4* s4 = (uint4*)sw;
        const uint4* gah = (const uint4*)(g_Ah + (size_t)row0 * Dn);
        const uint4* gbh = (const uint4*)(g_Bh + (size_t)col0 * Dn);
#pragma unroll
        for (int i = 0; i < 8; i++) {
            int idx = t + i * 256;
            int r = idx >> 4, q = idx & 15;
            s4[(WO_AH / 4) + r * 17 + q] = gah[r * 16 + q];
            s4[(WO_BH / 4) + r * 17 + q] = gbh[r * 16 + q];
        }
    }
    __syncthreads();

    int wr = w & 3;                    // row group: 4 x 32 rows
    int wc = w >> 2;                   // col group: 2 x 64 cols
    int rq = lane >> 2;                // groupID
    int tig = lane & 3;                // threadID_in_group
    int lrow = lane & 15;              // ldmatrix row-within-16
    int lkh = lane >> 4;               // ldmatrix k-half

    uint32_t acc[2][8][2];
#pragma unroll
    for (int mt = 0; mt < 2; mt++)
#pragma unroll
        for (int nt = 0; nt < 8; nt++) { acc[mt][nt][0] = 0u; acc[mt][nt][1] = 0u; }

    // per-lane ldmatrix base addresses
    uint32_t aad0 = sb + ((uint32_t)(WO_AH + (wr * 32 + lrow) * RW) << 2) + (lkh << 4);
    uint32_t aad1 = aad0 + ((16 * RW) << 2);
    uint32_t bad0 = sb + ((uint32_t)(WO_BH + (wc * 64 + lrow) * RW) << 2) + (lkh << 4);

#pragma unroll
    for (int ks = 0; ks < 8; ks++) {
        int kb = ks * 32;              // byte offset along k
        uint32_t ah[2][4];
        ldsm4(ah[0][0], ah[0][1], ah[0][2], ah[0][3], aad0 + kb);
        ldsm4(ah[1][0], ah[1][1], ah[1][2], ah[1][3], aad1 + kb);
        uint32_t badr = bad0 + kb;
#pragma unroll
        for (int ntp = 0; ntp < 4; ntp++) {
            uint32_t b0, b1, b2, b3;
            ldsm4(b0, b1, b2, b3, badr);
            badr += (16 * RW) << 2;
            // matrix order: cols0-7 klow, cols8-15 klow, cols0-7 khigh, cols8-15 khigh
            mma16816h(acc[0][2 * ntp],     ah[0], b0, b2);
            mma16816h(acc[0][2 * ntp + 1], ah[0], b1, b3);
            mma16816h(acc[1][2 * ntp],     ah[1], b0, b2);
            mma16816h(acc[1][2 * ntp + 1], ah[1], b1, b3);
        }
    }
    __syncthreads();   // tiles dead; smem reused for row-sum combine

    // ---- epilogue ----
    float rsp[4] = {0.f, 0.f, 0.f, 0.f};   // rows mt*16+rq, mt*16+8+rq
    float rsl[4] = {0.f, 0.f, 0.f, 0.f};
    int cq = tig * 2;
    int r0g = row0 + wr * 32 + rq;          // mt=0 row
    int lbl[4];                             // labels for rows r0g, +8, +16, +24
    lbl[0] = labels[r0g];
    lbl[1] = labels[r0g + 8];
    lbl[2] = labels[r0g + 16];
    lbl[3] = labels[r0g + 24];
#pragma unroll
    for (int nt = 0; nt < 8; nt++) {
        int col = col0 + wc * 64 + nt * 8 + cq;
        if (col >= Cn) continue;
        float2 b2 = *(const float2*)&bias[col];
#pragma unroll
        for (int mt = 0; mt < 2; mt++) {
            int r = r0g + mt * 16;
            float2 f0 = __half22float2(*(__half2*)&acc[mt][nt][0]);
            float2 f1 = __half22float2(*(__half2*)&acc[mt][nt][1]);
            float v00 = f0.x + b2.x, v01 = f0.y + b2.y;
            float v10 = f1.x + b2.x, v11 = f1.y + b2.y;
            // label capture (rare predicated stores, fp32-precise)
            if (lbl[2 * mt] == col)     g_wl[r] = v00;
            if (lbl[2 * mt] == col + 1) g_wl[r] = v01;
            if (lbl[2 * mt + 1] == col)     g_wl[r + 8] = v10;
            if (lbl[2 * mt + 1] == col + 1) g_wl[r + 8] = v11;
            float e00 = __expf(v00), e01 = __expf(v01);
            float e10 = __expf(v10), e11 = __expf(v11);
            *(__half2*)&g_q[(size_t)r * Cn + col] = __floats2half2_rn(e00, e01);
            *(__half2*)&g_q[(size_t)(r + 8) * Cn + col] = __floats2half2_rn(e10, e11);
            rsp[2 * mt]     += e00 + e01;
            rsp[2 * mt + 1] += e10 + e11;
            rsl[2 * mt]     += pow20(e00) + pow20(e01);
            rsl[2 * mt + 1] += pow20(e10) + pow20(e11);
        }
    }
    // reduce over the 4 lanes of each row group (tig bits)
#pragma unroll
    for (int j = 0; j < 4; j++) {
        rsp[j] += __shfl_xor_sync(0xffffffffu, rsp[j], 1);
        rsp[j] += __shfl_xor_sync(0xffffffffu, rsp[j], 2);
        rsl[j] += __shfl_xor_sync(0xffffffffu, rsl[j], 1);
        rsl[j] += __shfl_xor_sync(0xffffffffu, rsl[j], 2);
    }
    float* ssp = (float*)sw;           // [2][128]
    float* ssl = ((float*)sw) + 256;   // [2][128]
    if (tig == 0) {
#pragma unroll
        for (int j = 0; j < 4; j++) {
            int lr2 = wr * 32 + (j >> 1) * 16 + (j & 1) * 8 + rq;
            ssp[wc * 128 + lr2] = rsp[j];
            ssl[wc * 128 + lr2] = rsl[j];
        }
    }
    __syncthreads();
    if (t < 128) {
        g_psp[(size_t)(row0 + t) * NCT + ct] = ssp[t] + ssp[128 + t];
        g_psl[(size_t)(row0 + t) * NCT + ct] = ssl[t] + ssl[128 + t];
    }
}

// ---------------------------------------------------------------------------
// Per-row: sum partials, fix label term, compute inv + loss. Block per row.
// ---------------------------------------------------------------------------
__global__ __launch_bounds__(256) void row_final(const int* __restrict__ labels) {
    int row = blockIdx.x;
    int t = threadIdx.x;
    __shared__ float red[512];
    float sp = 0.f, sl = 0.f;
    const float* pp = g_psp + (size_t)row * NCT;
    const float* pl = g_psl + (size_t)row * NCT;
    for (int i = t; i < NCT; i += 256) { sp += pp[i]; sl += pl[i]; }
    red[t] = sp; red[256 + t] = sl;
    __syncthreads();
#pragma unroll
    for (int s = 128; s; s >>= 1) {
        if (t < s) { red[t] += red[t + s]; red[256 + t] += red[256 + t + s]; }
        __syncthreads();
    }
    if (t == 0) {
        float spr = red[0], slr = red[256];
        float wl = g_wl[row];
        float cc = fminf(fmaxf(wl, -1.0f + EPSf), 1.0f - EPSf);
        float cosm = cc * COS_M - sqrtf(fmaxf(1.0f - cc * cc, 0.0f)) * SIN_M;
        float total = slr - __expf(Sf * wl) + __expf(Sf * cosm);
        g_loss[row] = logf(total) - Sf * cosm;
        g_inv[row] = 1.0f / spr;
    }
}

// ---------------------------------------------------------------------------
// Elementwise: pred = q * inv[row]; no exp; streaming fp32 stores.
// ---------------------------------------------------------------------------
__global__ __launch_bounds__(256) void finalize(float* __restrict__ out) {
    int row = blockIdx.y;
    int i = blockIdx.x * 256 + threadIdx.x;         // group-of-4 index
    if (i >= Cn / 4) return;
    float inv = g_inv[row];
    const __half2* ph = (const __half2*)(g_q + (size_t)row * Cn + 4 * (size_t)i);
    __half2 h01 = ph[0], h23 = ph[1];
    float2 f01 = __half22float2(h01), f23 = __half22float2(h23);
    float4 v;
    v.x = f01.x * inv;
    v.y = f01.y * inv;
    v.z = f23.x * inv;
    v.w = f23.y * inv;
    st_cs_f4((float*)(out + (size_t)row * Cn) + 4 * (size_t)i, v);
}

// ---------------------------------------------------------------------------
__global__ __launch_bounds__(256) void loss_reduce(float* __restrict__ out) {
    __shared__ float red[256];
    int t = threadIdx.x;
    float s = 0.f;
    for (int i = t; i < Bn; i += 256) s += g_loss[i];
    red[t] = s; __syncthreads();
#pragma unroll
    for (int st = 128; st; st >>= 1) {
        if (t < st) red[t] += red[t + st];
        __syncthreads();
    }
    if (t == 0) out[(size_t)Bn * Cn] = red[0] / (float)Bn;
}

// ---------------------------------------------------------------------------
extern "C" void kernel_launch(void* const* d_in, const int* in_sizes, int n_in,
                              void* d_out, int out_size) {
    const float* x      = (const float*)d_in[0];
    const float* W      = (const float*)d_in[1];
    const float* bias   = (const float*)d_in[2];
    const int*   labels = (const int*)d_in[3];
    float* out = (float*)d_out;

    cudaFuncSetAttribute(gemm_mma, cudaFuncAttributeMaxDynamicSharedMemorySize,
                         SM_TOTAL);

    norm_quant<<<Bn / 8, 256>>>(x, Bn, Bn, 0);
    norm_quant<<<CPAD / 8, 256>>>(W, Cn, CPAD, 1);

    dim3 gg(NRT, NCT);   // row tile fastest -> each B tile loaded once
    gemm_mma<<<gg, 256, SM_TOTAL>>>(bias, labels);

    row_final<<<Bn, 256>>>(labels);

    dim3 gf((Cn / 4 + 255) / 256, Bn);
    finalize<<<gf, 256>>>(out);

    loss_reduce<<<1, 256>>>(out);
}

// round 15
// speedup vs baseline: 2.4025x; 1.0153x over previous
#include <cuda_runtime.h>
#include <cuda_bf16.h>
#include <cuda_fp16.h>
#include <math.h>
#include <stdint.h>

// Problem constants
#define Bn 2048
#define Cn 50000
#define Dn 128
#define CPAD 50048            // Cn padded: 128 * 391 exactly
#define NCT 391               // 128-wide column tiles
#define NRT (Bn / 128)        // 16 row tiles
#define Sf 20.0f
#define EPSf 1e-7f
#define COS_M 0.9950041652780258f
#define SIN_M 0.09983341664682815f

// fp16 scratch, plain row-major [row][128]
__device__ __align__(16) __half g_Ah[(size_t)Bn * Dn];
__device__ __align__(16) __half g_Bh[(size_t)CPAD * Dn];
// fp16 q = exp(wf) (205 MB)
__device__ __half g_q[(size_t)Bn * Cn];
// Per-(row, coltile) partial sums (written unconditionally -> no zeroing)
__device__ float g_psp[(size_t)Bn * NCT];   // sum exp(wf)
__device__ float g_psl[(size_t)Bn * NCT];   // sum exp(20*wf)
__device__ float g_wl[Bn];                  // wf at label column (fp32)
__device__ float g_inv[Bn];
__device__ float g_loss[Bn];

// ---------------------------------------------------------------------------
__device__ __forceinline__ uint32_t smem_u32(const void* p) {
    uint32_t a;
    asm("{ .reg .u64 t; cvta.to.shared.u64 t, %1; cvt.u32.u64 %0, t; }"
        : "=r"(a) : "l"(p));
    return a;
}
__device__ __forceinline__ void ldsm4(uint32_t& r0, uint32_t& r1, uint32_t& r2,
                                      uint32_t& r3, uint32_t addr) {
    asm volatile("ldmatrix.sync.aligned.m8n8.x4.shared.b16 {%0,%1,%2,%3}, [%4];"
                 : "=r"(r0), "=r"(r1), "=r"(r2), "=r"(r3) : "r"(addr));
}
// fp16-accumulator HMMA
__device__ __forceinline__ void mma16816h(uint32_t* c, const uint32_t* a,
                                          uint32_t b0, uint32_t b1) {
    asm volatile(
        "mma.sync.aligned.m16n8k16.row.col.f16.f16.f16.f16 "
        "{%0,%1}, {%2,%3,%4,%5}, {%6,%7}, {%0,%1};"
        : "+r"(c[0]), "+r"(c[1])
        : "r"(a[0]), "r"(a[1]), "r"(a[2]), "r"(a[3]), "r"(b0), "r"(b1));
}
__device__ __forceinline__ void st_cs_f4(float* p, float4 v) {
    asm volatile("st.global.cs.v4.f32 [%0], {%1,%2,%3,%4};"
                 :: "l"(p), "f"(v.x), "f"(v.y), "f"(v.z), "f"(v.w) : "memory");
}
__device__ __forceinline__ float pow20(float e) {
    float e2 = e * e;
    float e4 = e2 * e2;
    float e5 = e4 * e;
    float e10 = e5 * e5;
    return e10 * e10;
}

// ---------------------------------------------------------------------------
// Normalize -> single fp16 digit, plain row-major. One warp per row.
// Output array bound INSIDE device code (device symbols are invalid as
// host-side kernel args).
// ---------------------------------------------------------------------------
__global__ __launch_bounds__(256) void norm_quant(const float* __restrict__ in,
                                                  int nrows, int npad,
                                                  int which) {
    int warp = (blockIdx.x * blockDim.x + threadIdx.x) >> 5;
    int lane = threadIdx.x & 31;
    if (warp >= npad) return;
    float4 v = make_float4(0.f, 0.f, 0.f, 0.f);
    if (warp < nrows) v = ((const float4*)(in + (size_t)warp * Dn))[lane];
    float ss = v.x * v.x + v.y * v.y + v.z * v.z + v.w * v.w;
#pragma unroll
    for (int o = 16; o; o >>= 1) ss += __shfl_xor_sync(0xffffffffu, ss, o);
    float sc = 1.0f / fmaxf(sqrtf(ss), 1e-12f);
    if (warp >= nrows) sc = 0.0f;

    __half2 h01 = __floats2half2_rn(v.x * sc, v.y * sc);
    __half2 h23 = __floats2half2_rn(v.z * sc, v.w * sc);
    __half* dst = which ? g_Bh : g_Ah;
    size_t idx = (size_t)warp * Dn + 4 * lane;
    uint2 hv;
    hv.x = *(uint32_t*)&h01; hv.y = *(uint32_t*)&h23;
    *(uint2*)(dst + idx) = hv;
}

// ---------------------------------------------------------------------------
// fp16 mma GEMM (fp16 acc, ldmatrix fragments) with fused exp epilogue.
// CTA tile 128x128, 256 threads (8 warps of 32x64), K=128 staged in two
// 64-wide halves through one 36 KB buffer -> 4 CTAs/SM.
// SMEM as uint32 words, row stride 36 (32 data + 4 pad): 36864 bytes.
// ---------------------------------------------------------------------------
#define RW 36
#define WO_AH 0
#define WO_BH (128 * RW)
#define SM_WORDS (256 * RW)
#define SM_TOTAL (SM_WORDS * 4)

__global__ __launch_bounds__(256, 4) void gemm_mma(const float* __restrict__ bias,
                                                   const int* __restrict__ labels) {
    extern __shared__ uint32_t sw[];
    uint32_t sb = smem_u32(sw);
    int t = threadIdx.x;
    int w = t >> 5, lane = t & 31;
    int row0 = blockIdx.x * 128;       // row tile fastest: B tile L2-reused 16x
    int col0 = blockIdx.y * 128;
    int ct = blockIdx.y;

    int wr = w & 3;                    // row group: 4 x 32 rows
    int wc = w >> 2;                   // col group: 2 x 64 cols
    int rq = lane >> 2;                // groupID
    int tig = lane & 3;                // threadID_in_group
    int lrow = lane & 15;              // ldmatrix row-within-16
    int lkh = lane >> 4;               // ldmatrix k-half (16B)

    uint32_t acc[2][8][2];
#pragma unroll
    for (int mt = 0; mt < 2; mt++)
#pragma unroll
        for (int nt = 0; nt < 8; nt++) { acc[mt][nt][0] = 0u; acc[mt][nt][1] = 0u; }

    // per-lane ldmatrix base addresses (within the staged half)
    uint32_t aad0 = sb + ((uint32_t)(WO_AH + (wr * 32 + lrow) * RW) << 2) + (lkh << 4);
    uint32_t aad1 = aad0 + ((16 * RW) << 2);
    uint32_t bad0 = sb + ((uint32_t)(WO_BH + (wc * 64 + lrow) * RW) << 2) + (lkh << 4);

    const uint4* gah = (const uint4*)(g_Ah + (size_t)row0 * Dn);
    const uint4* gbh = (const uint4*)(g_Bh + (size_t)col0 * Dn);
    uint4* s4 = (uint4*)sw;

#pragma unroll
    for (int h = 0; h < 2; h++) {
        if (h) __syncthreads();        // mainloop of half 0 done before refill
        // copy half h: per matrix 128 rows x 8 uint4 (data) + 1 pad slot
#pragma unroll
        for (int i = 0; i < 4; i++) {
            int idx = t + i * 256;
            int r = idx >> 3, q = idx & 7;
            s4[r * 9 + q] = gah[r * 16 + 8 * h + q];
            s4[1152 + r * 9 + q] = gbh[r * 16 + 8 * h + q];
        }
        __syncthreads();

#pragma unroll
        for (int ks = 0; ks < 4; ks++) {
            int kb = ks * 32;          // byte offset within 128B half-row
            uint32_t ah[2][4];
            ldsm4(ah[0][0], ah[0][1], ah[0][2], ah[0][3], aad0 + kb);
            ldsm4(ah[1][0], ah[1][1], ah[1][2], ah[1][3], aad1 + kb);
            uint32_t badr = bad0 + kb;
#pragma unroll
            for (int ntp = 0; ntp < 4; ntp++) {
                uint32_t b0, b1, b2, b3;
                ldsm4(b0, b1, b2, b3, badr);
                badr += (16 * RW) << 2;
                mma16816h(acc[0][2 * ntp],     ah[0], b0, b2);
                mma16816h(acc[0][2 * ntp + 1], ah[0], b1, b3);
                mma16816h(acc[1][2 * ntp],     ah[1], b0, b2);
                mma16816h(acc[1][2 * ntp + 1], ah[1], b1, b3);
            }
        }
    }
    __syncthreads();   // tiles dead; smem reused for row-sum combine

    // ---- epilogue ----
    float rsp[4] = {0.f, 0.f, 0.f, 0.f};   // rows mt*16+rq, mt*16+8+rq
    float rsl[4] = {0.f, 0.f, 0.f, 0.f};
    int cq = tig * 2;
    int r0g = row0 + wr * 32 + rq;          // mt=0 row
    int lbl[4];                             // labels for rows r0g, +8, +16, +24
    lbl[0] = labels[r0g];
    lbl[1] = labels[r0g + 8];
    lbl[2] = labels[r0g + 16];
    lbl[3] = labels[r0g + 24];
#pragma unroll
    for (int nt = 0; nt < 8; nt++) {
        int col = col0 + wc * 64 + nt * 8 + cq;
        if (col >= Cn) continue;
        float2 b2 = *(const float2*)&bias[col];
#pragma unroll
        for (int mt = 0; mt < 2; mt++) {
            int r = r0g + mt * 16;
            float2 f0 = __half22float2(*(__half2*)&acc[mt][nt][0]);
            float2 f1 = __half22float2(*(__half2*)&acc[mt][nt][1]);
            float v00 = f0.x + b2.x, v01 = f0.y + b2.y;
            float v10 = f1.x + b2.x, v11 = f1.y + b2.y;
            // label capture (rare predicated stores, fp32-precise)
            if (lbl[2 * mt] == col)     g_wl[r] = v00;
            if (lbl[2 * mt] == col + 1) g_wl[r] = v01;
            if (lbl[2 * mt + 1] == col)     g_wl[r + 8] = v10;
            if (lbl[2 * mt + 1] == col + 1) g_wl[r + 8] = v11;
            float e00 = __expf(v00), e01 = __expf(v01);
            float e10 = __expf(v10), e11 = __expf(v11);
            *(__half2*)&g_q[(size_t)r * Cn + col] = __floats2half2_rn(e00, e01);
            *(__half2*)&g_q[(size_t)(r + 8) * Cn + col] = __floats2half2_rn(e10, e11);
            rsp[2 * mt]     += e00 + e01;
            rsp[2 * mt + 1] += e10 + e11;
            rsl[2 * mt]     += pow20(e00) + pow20(e01);
            rsl[2 * mt + 1] += pow20(e10) + pow20(e11);
        }
    }
    // reduce over the 4 lanes of each row group (tig bits)
#pragma unroll
    for (int j = 0; j < 4; j++) {
        rsp[j] += __shfl_xor_sync(0xffffffffu, rsp[j], 1);
        rsp[j] += __shfl_xor_sync(0xffffffffu, rsp[j], 2);
        rsl[j] += __shfl_xor_sync(0xffffffffu, rsl[j], 1);
        rsl[j] += __shfl_xor_sync(0xffffffffu, rsl[j], 2);
    }
    float* ssp = (float*)sw;           // [2][128]
    float* ssl = ((float*)sw) + 256;   // [2][128]
    if (tig == 0) {
#pragma unroll
        for (int j = 0; j < 4; j++) {
            int lr2 = wr * 32 + (j >> 1) * 16 + (j & 1) * 8 + rq;
            ssp[wc * 128 + lr2] = rsp[j];
            ssl[wc * 128 + lr2] = rsl[j];
        }
    }
    __syncthreads();
    if (t < 128) {
        g_psp[(size_t)(row0 + t) * NCT + ct] = ssp[t] + ssp[128 + t];
        g_psl[(size_t)(row0 + t) * NCT + ct] = ssl[t] + ssl[128 + t];
    }
}

// ---------------------------------------------------------------------------
// Per-row: sum partials, fix label term, compute inv + loss. Block per row.
// ---------------------------------------------------------------------------
__global__ __launch_bounds__(256) void row_final(const int* __restrict__ labels) {
    int row = blockIdx.x;
    int t = threadIdx.x;
    __shared__ float red[512];
    float sp = 0.f, sl = 0.f;
    const float* pp = g_psp + (size_t)row * NCT;
    const float* pl = g_psl + (size_t)row * NCT;
    for (int i = t; i < NCT; i += 256) { sp += pp[i]; sl += pl[i]; }
    red[t] = sp; red[256 + t] = sl;
    __syncthreads();
#pragma unroll
    for (int s = 128; s; s >>= 1) {
        if (t < s) { red[t] += red[t + s]; red[256 + t] += red[256 + t + s]; }
        __syncthreads();
    }
    if (t == 0) {
        float spr = red[0], slr = red[256];
        float wl = g_wl[row];
        float cc = fminf(fmaxf(wl, -1.0f + EPSf), 1.0f - EPSf);
        float cosm = cc * COS_M - sqrtf(fmaxf(1.0f - cc * cc, 0.0f)) * SIN_M;
        float total = slr - __expf(Sf * wl) + __expf(Sf * cosm);
        g_loss[row] = logf(total) - Sf * cosm;
        g_inv[row] = 1.0f / spr;
    }
}

// ---------------------------------------------------------------------------
// Elementwise: pred = q * inv[row]; no exp; streaming fp32 stores.
// ---------------------------------------------------------------------------
__global__ __launch_bounds__(256) void finalize(float* __restrict__ out) {
    int row = blockIdx.y;
    int i = blockIdx.x * 256 + threadIdx.x;         // group-of-4 index
    if (i >= Cn / 4) return;
    float inv = g_inv[row];
    const __half2* ph = (const __half2*)(g_q + (size_t)row * Cn + 4 * (size_t)i);
    __half2 h01 = ph[0], h23 = ph[1];
    float2 f01 = __half22float2(h01), f23 = __half22float2(h23);
    float4 v;
    v.x = f01.x * inv;
    v.y = f01.y * inv;
    v.z = f23.x * inv;
    v.w = f23.y * inv;
    st_cs_f4((float*)(out + (size_t)row * Cn) + 4 * (size_t)i, v);
}

// ---------------------------------------------------------------------------
__global__ __launch_bounds__(256) void loss_reduce(float* __restrict__ out) {
    __shared__ float red[256];
    int t = threadIdx.x;
    float s = 0.f;
    for (int i = t; i < Bn; i += 256) s += g_loss[i];
    red[t] = s; __syncthreads();
#pragma unroll
    for (int st = 128; st; st >>= 1) {
        if (t < st) red[t] += red[t + st];
        __syncthreads();
    }
    if (t == 0) out[(size_t)Bn * Cn] = red[0] / (float)Bn;
}

// ---------------------------------------------------------------------------
extern "C" void kernel_launch(void* const* d_in, const int* in_sizes, int n_in,
                              void* d_out, int out_size) {
    const float* x      = (const float*)d_in[0];
    const float* W      = (const float*)d_in[1];
    const float* bias   = (const float*)d_in[2];
    const int*   labels = (const int*)d_in[3];
    float* out = (float*)d_out;

    cudaFuncSetAttribute(gemm_mma, cudaFuncAttributeMaxDynamicSharedMemorySize,
                         SM_TOTAL);

    norm_quant<<<Bn / 8, 256>>>(x, Bn, Bn, 0);
    norm_quant<<<CPAD / 8, 256>>>(W, Cn, CPAD, 1);

    dim3 gg(NRT, NCT);   // row tile fastest -> each B tile loaded once
    gemm_mma<<<gg, 256, SM_TOTAL>>>(bias, labels);

    row_final<<<Bn, 256>>>(labels);

    dim3 gf((Cn / 4 + 255) / 256, Bn);
    finalize<<<gf, 256>>>(out);

    loss_reduce<<<1, 256>>>(out);
}